// round 1
// baseline (speedup 1.0000x reference)
#include <cuda_runtime.h>

#define SEQ    720
#define DIM    2048
#define NH     16
#define HD     128
#define CACHE  11520
#define LSTART 720
#define LEND   1440

// Scratch (device globals: allocation-free rule)
__device__ float g_q[SEQ * DIM];
__device__ float g_k[SEQ * DIM];
__device__ float g_v[SEQ * DIM];
__device__ float g_attn[SEQ * DIM];

// ---------------------------------------------------------------------------
// GEMM (NT): C[m,n] = bias[n] + sum_k A[m,k] * B[n,k]
// BM=BN=128, BK=8, 256 threads, 8x8 per thread, transposed smem tiles.
// gridDim.z selects one of up to 3 (B, bias, C) sets (fused QKV).
// ---------------------------------------------------------------------------
struct GemmSet {
    const float* B;
    const float* bias;
    float* C;
};

__global__ __launch_bounds__(256, 2) void gemm_nt(
    const float* __restrict__ A, GemmSet s0, GemmSet s1, GemmSet s2,
    int M, int N, int K)
{
    GemmSet s = (blockIdx.z == 0) ? s0 : ((blockIdx.z == 1) ? s1 : s2);

    __shared__ float As[8 * 132];
    __shared__ float Bs[8 * 132];

    const int tid = threadIdx.x;
    const int bm = blockIdx.y * 128;
    const int bn = blockIdx.x * 128;
    const int m0 = (tid >> 4) * 8;
    const int n0 = (tid & 15) * 8;
    const int lr = tid >> 1;
    const int lc = (tid & 1) * 4;

    float acc[8][8];
#pragma unroll
    for (int i = 0; i < 8; i++)
#pragma unroll
        for (int j = 0; j < 8; j++) acc[i][j] = 0.f;

    const bool aok = (bm + lr) < M;
    const float* Ap = A + (size_t)(bm + lr) * K + lc;
    const float* Bp = s.B + (size_t)(bn + lr) * K + lc;

    for (int k0 = 0; k0 < K; k0 += 8) {
        float4 av = aok ? *(const float4*)(Ap + k0) : make_float4(0.f, 0.f, 0.f, 0.f);
        float4 bv = *(const float4*)(Bp + k0);
        As[(lc + 0) * 132 + lr] = av.x;
        As[(lc + 1) * 132 + lr] = av.y;
        As[(lc + 2) * 132 + lr] = av.z;
        As[(lc + 3) * 132 + lr] = av.w;
        Bs[(lc + 0) * 132 + lr] = bv.x;
        Bs[(lc + 1) * 132 + lr] = bv.y;
        Bs[(lc + 2) * 132 + lr] = bv.z;
        Bs[(lc + 3) * 132 + lr] = bv.w;
        __syncthreads();
#pragma unroll
        for (int kk = 0; kk < 8; kk++) {
            float4 a0 = *(const float4*)&As[kk * 132 + m0];
            float4 a1 = *(const float4*)&As[kk * 132 + m0 + 4];
            float4 b0 = *(const float4*)&Bs[kk * 132 + n0];
            float4 b1 = *(const float4*)&Bs[kk * 132 + n0 + 4];
            float aa[8] = {a0.x, a0.y, a0.z, a0.w, a1.x, a1.y, a1.z, a1.w};
            float bb[8] = {b0.x, b0.y, b0.z, b0.w, b1.x, b1.y, b1.z, b1.w};
#pragma unroll
            for (int i = 0; i < 8; i++)
#pragma unroll
                for (int j = 0; j < 8; j++) acc[i][j] += aa[i] * bb[j];
        }
        __syncthreads();
    }

#pragma unroll
    for (int i = 0; i < 8; i++) {
        int row = bm + m0 + i;
        if (row < M) {
            float* cp = s.C + (size_t)row * N + bn + n0;
            const float* bp = s.bias + bn + n0;
            float4 c0 = make_float4(acc[i][0] + bp[0], acc[i][1] + bp[1],
                                    acc[i][2] + bp[2], acc[i][3] + bp[3]);
            float4 c1 = make_float4(acc[i][4] + bp[4], acc[i][5] + bp[5],
                                    acc[i][6] + bp[6], acc[i][7] + bp[7]);
            *(float4*)(cp) = c0;
            *(float4*)(cp + 4) = c1;
        }
    }
}

// ---------------------------------------------------------------------------
// RMSNorm + RoPE, in place on g_q (blockIdx.y=0) / g_k (blockIdx.y=1)
// ---------------------------------------------------------------------------
__global__ __launch_bounds__(256) void rmsnorm_rope(
    const float* __restrict__ wq, const float* __restrict__ wk,
    const float* __restrict__ fc, const float* __restrict__ fs)
{
    const int s = blockIdx.x;
    float* row = (blockIdx.y == 0 ? g_q : g_k) + s * DIM;
    const float* w = (blockIdx.y == 0) ? wq : wk;
    const int tid = threadIdx.x;

    float4 v0 = ((const float4*)row)[tid * 2];
    float4 v1 = ((const float4*)row)[tid * 2 + 1];
    float ss = v0.x * v0.x + v0.y * v0.y + v0.z * v0.z + v0.w * v0.w +
               v1.x * v1.x + v1.y * v1.y + v1.z * v1.z + v1.w * v1.w;
#pragma unroll
    for (int o = 16; o > 0; o >>= 1) ss += __shfl_xor_sync(0xffffffffu, ss, o);

    __shared__ float red[8];
    __shared__ float stot;
    if ((tid & 31) == 0) red[tid >> 5] = ss;
    __syncthreads();
    if (tid == 0) {
        float t = 0.f;
#pragma unroll
        for (int i = 0; i < 8; i++) t += red[i];
        stot = t;
    }
    __syncthreads();
    const float r = rsqrtf(stot * (1.0f / DIM) + 1e-6f);

    const int e = tid * 8;
    float xv[8] = {v0.x, v0.y, v0.z, v0.w, v1.x, v1.y, v1.z, v1.w};
    float ov[8];
#pragma unroll
    for (int i = 0; i < 4; i++) {
        int e0 = e + 2 * i;
        int j = (e0 & 127) >> 1;
        float c = fc[s * 64 + j];
        float sn = fs[s * 64 + j];
        float a = xv[2 * i] * r * w[e0];
        float b = xv[2 * i + 1] * r * w[e0 + 1];
        ov[2 * i] = a * c - b * sn;
        ov[2 * i + 1] = a * sn + b * c;
    }
    ((float4*)row)[tid * 2] = make_float4(ov[0], ov[1], ov[2], ov[3]);
    ((float4*)row)[tid * 2 + 1] = make_float4(ov[4], ov[5], ov[6], ov[7]);
}

// ---------------------------------------------------------------------------
// Flash attention (fp32, online softmax).
// Block = (64-query tile, head). 180 key blocks of 64.
// Cache rows [720,1440) are substituted from freshly computed g_k/g_v.
// smem: Qst[128][64] (transposed, pre-scaled) | Ks[64][132] (Ss aliases) |
//       Vs[64][132] | Mi/Li/Al[64]  = 101120 B -> 2 blocks/SM
// ---------------------------------------------------------------------------
__global__ __launch_bounds__(256, 2) void attn_kernel(
    const float* __restrict__ cache_k, const float* __restrict__ cache_v)
{
    extern __shared__ float sm[];
    float* Qst = sm;               // 128*64 = 8192
    float* Ks  = sm + 8192;        // 64*132 = 8448
    float* Ss  = Ks;               // alias (64*65 = 4160 <= 8448)
    float* Vs  = sm + 8192 + 8448; // 64*132 = 8448
    float* Mi  = sm + 25088;
    float* Li  = Mi + 64;
    float* Al  = Li + 64;

    const int tid = threadIdx.x;
    const int h = blockIdx.y;
    const int qb = blockIdx.x * 64;
    const float scale = 0.08838834764831845f;  // 128^-0.5

    // Load Q tile transposed + pre-scaled
#pragma unroll
    for (int i = 0; i < 8; i++) {
        int t = tid + i * 256;
        int row = t >> 5;
        int d4 = (t & 31) * 4;
        float4 v = make_float4(0.f, 0.f, 0.f, 0.f);
        int qr = qb + row;
        if (qr < SEQ) v = *(const float4*)(g_q + qr * DIM + h * HD + d4);
        Qst[(d4 + 0) * 64 + row] = v.x * scale;
        Qst[(d4 + 1) * 64 + row] = v.y * scale;
        Qst[(d4 + 2) * 64 + row] = v.z * scale;
        Qst[(d4 + 3) * 64 + row] = v.w * scale;
    }
    if (tid < 64) { Mi[tid] = -1e30f; Li[tid] = 0.f; }

    const int m0 = (tid & 15) * 4;
    const int n0 = (tid >> 4) * 4;
    const int d0 = (tid >> 4) * 8;
    float acc[4][8];
#pragma unroll
    for (int i = 0; i < 4; i++)
#pragma unroll
        for (int j = 0; j < 8; j++) acc[i][j] = 0.f;
    __syncthreads();

    for (int kb = 0; kb < CACHE / 64; kb++) {
        const int base = kb * 64;
        // Load K/V tiles (row-major, coalesced)
#pragma unroll
        for (int i = 0; i < 8; i++) {
            int t = tid + i * 256;
            int row = t >> 5;
            int d4 = (t & 31) * 4;
            int kk = base + row;
            const float* kp;
            const float* vp;
            if (kk >= LSTART && kk < LEND) {
                int rr = kk - LSTART;
                kp = g_k + rr * DIM + h * HD;
                vp = g_v + rr * DIM + h * HD;
            } else {
                size_t off = ((size_t)kk * NH + h) * HD;
                kp = cache_k + off;
                vp = cache_v + off;
            }
            *(float4*)&Ks[row * 132 + d4] = *(const float4*)(kp + d4);
            *(float4*)&Vs[row * 132 + d4] = *(const float4*)(vp + d4);
        }
        __syncthreads();

        // S = Q @ K^T  (64x64x128), 4x4 per thread
        float sc[4][4];
#pragma unroll
        for (int i = 0; i < 4; i++)
#pragma unroll
            for (int j = 0; j < 4; j++) sc[i][j] = 0.f;
#pragma unroll 8
        for (int kd = 0; kd < 128; kd++) {
            float4 qv = *(const float4*)&Qst[kd * 64 + m0];
            float k0v = Ks[(n0 + 0) * 132 + kd];
            float k1v = Ks[(n0 + 1) * 132 + kd];
            float k2v = Ks[(n0 + 2) * 132 + kd];
            float k3v = Ks[(n0 + 3) * 132 + kd];
            sc[0][0] += qv.x * k0v; sc[0][1] += qv.x * k1v; sc[0][2] += qv.x * k2v; sc[0][3] += qv.x * k3v;
            sc[1][0] += qv.y * k0v; sc[1][1] += qv.y * k1v; sc[1][2] += qv.y * k2v; sc[1][3] += qv.y * k3v;
            sc[2][0] += qv.z * k0v; sc[2][1] += qv.z * k1v; sc[2][2] += qv.z * k2v; sc[2][3] += qv.z * k3v;
            sc[3][0] += qv.w * k0v; sc[3][1] += qv.w * k1v; sc[3][2] += qv.w * k2v; sc[3][3] += qv.w * k3v;
        }
        __syncthreads();  // all Ks reads done before Ss (alias) writes

#pragma unroll
        for (int i = 0; i < 4; i++)
#pragma unroll
            for (int j = 0; j < 4; j++) Ss[(m0 + i) * 65 + n0 + j] = sc[i][j];
        __syncthreads();

        // Online softmax: 4 threads per row, 16 cols each
        {
            int r = tid >> 2;
            int jj = tid & 3;
            float* srow = Ss + r * 65 + jj * 16;
            float mx = srow[0];
#pragma unroll
            for (int c = 1; c < 16; c++) mx = fmaxf(mx, srow[c]);
            mx = fmaxf(mx, __shfl_xor_sync(0xffffffffu, mx, 1));
            mx = fmaxf(mx, __shfl_xor_sync(0xffffffffu, mx, 2));
            float oldm = Mi[r];
            float newm = fmaxf(oldm, mx);
            float sum = 0.f;
#pragma unroll
            for (int c = 0; c < 16; c++) {
                float p = __expf(srow[c] - newm);
                srow[c] = p;
                sum += p;
            }
            sum += __shfl_xor_sync(0xffffffffu, sum, 1);
            sum += __shfl_xor_sync(0xffffffffu, sum, 2);
            if (jj == 0) {
                Al[r] = __expf(oldm - newm);
                Mi[r] = newm;
                Li[r] = Li[r] * Al[r] + sum;
            }
        }
        __syncthreads();

        // Rescale accumulators, then O += P @ V (64x128x64), 4x8 per thread
        {
            float a0 = Al[m0 + 0], a1 = Al[m0 + 1], a2 = Al[m0 + 2], a3 = Al[m0 + 3];
#pragma unroll
            for (int j = 0; j < 8; j++) {
                acc[0][j] *= a0; acc[1][j] *= a1; acc[2][j] *= a2; acc[3][j] *= a3;
            }
        }
#pragma unroll 4
        for (int nk = 0; nk < 64; nk++) {
            float4 v0 = *(const float4*)&Vs[nk * 132 + d0];
            float4 v1 = *(const float4*)&Vs[nk * 132 + d0 + 4];
            float p0 = Ss[(m0 + 0) * 65 + nk];
            float p1 = Ss[(m0 + 1) * 65 + nk];
            float p2 = Ss[(m0 + 2) * 65 + nk];
            float p3 = Ss[(m0 + 3) * 65 + nk];
            float va[8] = {v0.x, v0.y, v0.z, v0.w, v1.x, v1.y, v1.z, v1.w};
#pragma unroll
            for (int j = 0; j < 8; j++) {
                acc[0][j] += p0 * va[j];
                acc[1][j] += p1 * va[j];
                acc[2][j] += p2 * va[j];
                acc[3][j] += p3 * va[j];
            }
        }
        __syncthreads();
    }

    // Final normalize + store
#pragma unroll
    for (int i = 0; i < 4; i++) {
        int row = qb + m0 + i;
        if (row < SEQ) {
            float inv = 1.f / Li[m0 + i];
            float4 o0 = make_float4(acc[i][0] * inv, acc[i][1] * inv,
                                    acc[i][2] * inv, acc[i][3] * inv);
            float4 o1 = make_float4(acc[i][4] * inv, acc[i][5] * inv,
                                    acc[i][6] * inv, acc[i][7] * inv);
            *(float4*)(g_attn + row * DIM + h * HD + d0) = o0;
            *(float4*)(g_attn + row * DIM + h * HD + d0 + 4) = o1;
        }
    }
}

// ---------------------------------------------------------------------------
extern "C" void kernel_launch(void* const* d_in, const int* in_sizes, int n_in,
                              void* d_out, int out_size)
{
    const float* x    = (const float*)d_in[0];
    const float* q_w  = (const float*)d_in[1];
    const float* q_b  = (const float*)d_in[2];
    const float* k_w  = (const float*)d_in[3];
    const float* k_b  = (const float*)d_in[4];
    const float* v_w  = (const float*)d_in[5];
    const float* v_b  = (const float*)d_in[6];
    const float* o_w  = (const float*)d_in[7];
    const float* o_b  = (const float*)d_in[8];
    const float* nqw  = (const float*)d_in[9];
    const float* nkw  = (const float*)d_in[10];
    const float* ck   = (const float*)d_in[11];
    const float* cv   = (const float*)d_in[12];
    const float* fc   = (const float*)d_in[13];
    const float* fs   = (const float*)d_in[14];

    float *dq, *dk, *dv, *da;
    cudaGetSymbolAddress((void**)&dq, g_q);
    cudaGetSymbolAddress((void**)&dk, g_k);
    cudaGetSymbolAddress((void**)&dv, g_v);
    cudaGetSymbolAddress((void**)&da, g_attn);

    // Fused QKV projection
    GemmSet sq{q_w, q_b, dq}, sk{k_w, k_b, dk}, sv{v_w, v_b, dv};
    gemm_nt<<<dim3(16, 6, 3), 256>>>(x, sq, sk, sv, SEQ, DIM, DIM);

    // RMSNorm + RoPE (q and k, in place)
    rmsnorm_rope<<<dim3(SEQ, 2), 256>>>(nqw, nkw, fc, fs);

    // Attention
    const int ATTN_SMEM = 101120;
    cudaFuncSetAttribute(attn_kernel, cudaFuncAttributeMaxDynamicSharedMemorySize,
                         ATTN_SMEM);
    attn_kernel<<<dim3(12, NH), 256, ATTN_SMEM>>>(ck, cv);

    // Output projection -> d_out
    GemmSet so{o_w, o_b, (float*)d_out};
    gemm_nt<<<dim3(16, 6, 1), 256>>>(da, so, so, so, SEQ, DIM, DIM);
}

// round 2
// speedup vs baseline: 3.4973x; 3.4973x over previous
#include <cuda_runtime.h>

#define SEQ    720
#define DIM    2048
#define NH     16
#define HD     128
#define CACHE  11520
#define LSTART 720
#define LEND   1440
#define KVSPLIT 3
#define KB_PER_SPLIT (CACHE / KVSPLIT / 64)   // 60

// Scratch (device globals: allocation-free rule)
__device__ float g_q[SEQ * DIM];
__device__ float g_k[SEQ * DIM];
__device__ float g_v[SEQ * DIM];
__device__ float g_attn[SEQ * DIM];
__device__ float g_part[KVSPLIT * SEQ * DIM];
__device__ float g_m[KVSPLIT * NH * SEQ];
__device__ float g_l[KVSPLIT * NH * SEQ];

// ---------------------------------------------------------------------------
// tf32 helpers
// ---------------------------------------------------------------------------
__device__ __forceinline__ unsigned cvt_tf32(float x) {
    unsigned r;
    asm("cvt.rna.tf32.f32 %0, %1;" : "=r"(r) : "f"(x));
    return r;
}

__device__ __forceinline__ void mma_tf32(float* c, unsigned a0, unsigned a1,
                                         unsigned a2, unsigned a3,
                                         unsigned b0, unsigned b1) {
    asm volatile(
        "mma.sync.aligned.m16n8k8.row.col.f32.tf32.tf32.f32 "
        "{%0,%1,%2,%3},{%4,%5,%6,%7},{%8,%9},{%0,%1,%2,%3};\n"
        : "+f"(c[0]), "+f"(c[1]), "+f"(c[2]), "+f"(c[3])
        : "r"(a0), "r"(a1), "r"(a2), "r"(a3), "r"(b0), "r"(b1));
}

// ---------------------------------------------------------------------------
// GEMM (NT, tf32 tensor cores): C[m,n] = bias[n] + sum_k A[m,k] * B[n,k]
// BM=BN=128, BK=16, 256 threads (8 warps, 2x4), warp tile 64x32, m16n8k8.
// N = K = 2048 fixed. gridDim.z selects the (B, bias, C) set (fused QKV).
// ---------------------------------------------------------------------------
struct GemmSet {
    const float* B;
    const float* bias;
    float* C;
};

__global__ __launch_bounds__(256, 2) void gemm_tf32(
    const float* __restrict__ A, GemmSet s0, GemmSet s1, GemmSet s2, int M)
{
    GemmSet s = (blockIdx.z == 0) ? s0 : ((blockIdx.z == 1) ? s1 : s2);

    __shared__ unsigned As[128 * 20];
    __shared__ unsigned Bs[128 * 20];

    const int tid  = threadIdx.x;
    const int lane = tid & 31;
    const int wid  = tid >> 5;
    const int wm   = wid >> 2;       // 0..1
    const int wn   = wid & 3;        // 0..3
    const int lr   = lane >> 2;      // 0..7
    const int lc   = lane & 3;       // 0..3
    const int bm = blockIdx.y * 128;
    const int bn = blockIdx.x * 128;

    const int r  = tid >> 2;         // 0..63
    const int c4 = (tid & 3) * 4;

    float acc[4][4][4];
#pragma unroll
    for (int i = 0; i < 4; i++)
#pragma unroll
        for (int j = 0; j < 4; j++)
#pragma unroll
            for (int q = 0; q < 4; q++) acc[i][j][q] = 0.f;

    const bool a0ok = (bm + r) < M;
    const bool a1ok = (bm + r + 64) < M;
    const float* Ap0 = A + (size_t)(bm + r) * 2048 + c4;
    const float* Ap1 = A + (size_t)(bm + r + 64) * 2048 + c4;
    const float* Bp0 = s.B + (size_t)(bn + r) * 2048 + c4;
    const float* Bp1 = s.B + (size_t)(bn + r + 64) * 2048 + c4;

    float4 ra0 = a0ok ? *(const float4*)Ap0 : make_float4(0, 0, 0, 0);
    float4 ra1 = a1ok ? *(const float4*)Ap1 : make_float4(0, 0, 0, 0);
    float4 rb0 = *(const float4*)Bp0;
    float4 rb1 = *(const float4*)Bp1;

    for (int k0 = 0; k0 < 2048; k0 += 16) {
        // store current tiles (cvt to tf32)
        unsigned* as0 = As + r * 20 + c4;
        as0[0] = cvt_tf32(ra0.x); as0[1] = cvt_tf32(ra0.y);
        as0[2] = cvt_tf32(ra0.z); as0[3] = cvt_tf32(ra0.w);
        unsigned* as1 = As + (r + 64) * 20 + c4;
        as1[0] = cvt_tf32(ra1.x); as1[1] = cvt_tf32(ra1.y);
        as1[2] = cvt_tf32(ra1.z); as1[3] = cvt_tf32(ra1.w);
        unsigned* bs0 = Bs + r * 20 + c4;
        bs0[0] = cvt_tf32(rb0.x); bs0[1] = cvt_tf32(rb0.y);
        bs0[2] = cvt_tf32(rb0.z); bs0[3] = cvt_tf32(rb0.w);
        unsigned* bs1 = Bs + (r + 64) * 20 + c4;
        bs1[0] = cvt_tf32(rb1.x); bs1[1] = cvt_tf32(rb1.y);
        bs1[2] = cvt_tf32(rb1.z); bs1[3] = cvt_tf32(rb1.w);
        __syncthreads();

        // prefetch next tiles
        if (k0 + 16 < 2048) {
            ra0 = a0ok ? *(const float4*)(Ap0 + k0 + 16) : make_float4(0, 0, 0, 0);
            ra1 = a1ok ? *(const float4*)(Ap1 + k0 + 16) : make_float4(0, 0, 0, 0);
            rb0 = *(const float4*)(Bp0 + k0 + 16);
            rb1 = *(const float4*)(Bp1 + k0 + 16);
        }

#pragma unroll
        for (int kk = 0; kk < 2; kk++) {
            unsigned af[4][4];
            unsigned bf[4][2];
#pragma unroll
            for (int mt = 0; mt < 4; mt++) {
                const unsigned* ab = As + (wm * 64 + mt * 16 + lr) * 20 + kk * 8 + lc;
                af[mt][0] = ab[0];
                af[mt][1] = ab[8 * 20];
                af[mt][2] = ab[4];
                af[mt][3] = ab[8 * 20 + 4];
            }
#pragma unroll
            for (int nt = 0; nt < 4; nt++) {
                const unsigned* bb = Bs + (wn * 32 + nt * 8 + lr) * 20 + kk * 8 + lc;
                bf[nt][0] = bb[0];
                bf[nt][1] = bb[4];
            }
#pragma unroll
            for (int mt = 0; mt < 4; mt++)
#pragma unroll
                for (int nt = 0; nt < 4; nt++)
                    mma_tf32(acc[mt][nt], af[mt][0], af[mt][1], af[mt][2], af[mt][3],
                             bf[nt][0], bf[nt][1]);
        }
        __syncthreads();
    }

    // epilogue: bias add + store
#pragma unroll
    for (int mt = 0; mt < 4; mt++) {
        int row = bm + wm * 64 + mt * 16 + lr;
#pragma unroll
        for (int nt = 0; nt < 4; nt++) {
            int col = bn + wn * 32 + nt * 8 + 2 * lc;
            float b0v = s.bias[col], b1v = s.bias[col + 1];
            if (row < M) {
                float2 o = make_float2(acc[mt][nt][0] + b0v, acc[mt][nt][1] + b1v);
                *(float2*)(s.C + (size_t)row * 2048 + col) = o;
            }
            if (row + 8 < M) {
                float2 o = make_float2(acc[mt][nt][2] + b0v, acc[mt][nt][3] + b1v);
                *(float2*)(s.C + (size_t)(row + 8) * 2048 + col) = o;
            }
        }
    }
}

// ---------------------------------------------------------------------------
// RMSNorm + RoPE, in place on g_q (blockIdx.y=0) / g_k (blockIdx.y=1)
// ---------------------------------------------------------------------------
__global__ __launch_bounds__(256) void rmsnorm_rope(
    const float* __restrict__ wq, const float* __restrict__ wk,
    const float* __restrict__ fc, const float* __restrict__ fs)
{
    const int s = blockIdx.x;
    float* row = (blockIdx.y == 0 ? g_q : g_k) + s * DIM;
    const float* w = (blockIdx.y == 0) ? wq : wk;
    const int tid = threadIdx.x;

    float4 v0 = ((const float4*)row)[tid * 2];
    float4 v1 = ((const float4*)row)[tid * 2 + 1];
    float ss = v0.x * v0.x + v0.y * v0.y + v0.z * v0.z + v0.w * v0.w +
               v1.x * v1.x + v1.y * v1.y + v1.z * v1.z + v1.w * v1.w;
#pragma unroll
    for (int o = 16; o > 0; o >>= 1) ss += __shfl_xor_sync(0xffffffffu, ss, o);

    __shared__ float red[8];
    __shared__ float stot;
    if ((tid & 31) == 0) red[tid >> 5] = ss;
    __syncthreads();
    if (tid == 0) {
        float t = 0.f;
#pragma unroll
        for (int i = 0; i < 8; i++) t += red[i];
        stot = t;
    }
    __syncthreads();
    const float r = rsqrtf(stot * (1.0f / DIM) + 1e-6f);

    const int e = tid * 8;
    float xv[8] = {v0.x, v0.y, v0.z, v0.w, v1.x, v1.y, v1.z, v1.w};
    float ov[8];
#pragma unroll
    for (int i = 0; i < 4; i++) {
        int e0 = e + 2 * i;
        int j = (e0 & 127) >> 1;
        float c = fc[s * 64 + j];
        float sn = fs[s * 64 + j];
        float a = xv[2 * i] * r * w[e0];
        float b = xv[2 * i + 1] * r * w[e0 + 1];
        ov[2 * i] = a * c - b * sn;
        ov[2 * i + 1] = a * sn + b * c;
    }
    ((float4*)row)[tid * 2] = make_float4(ov[0], ov[1], ov[2], ov[3]);
    ((float4*)row)[tid * 2 + 1] = make_float4(ov[4], ov[5], ov[6], ov[7]);
}

// ---------------------------------------------------------------------------
// Flash attention, tf32 tensor cores, online softmax, KV-split=3.
// Block = (64-query tile, head, split). Each split covers 60 key-blocks of 64.
// 8 warps. S: warp grid 4x2 (m16 x n32). PV: 4x2 (m16 x n64).
// smem (u32 words): Qs 64x132 | Ks 64x132 (S fp32 64x68 aliases) |
//                   Vs 64x136 | Mi/Li/Al 64 each  -> 103168 B, 2 blocks/SM
// ---------------------------------------------------------------------------
__global__ __launch_bounds__(256, 2) void attn_tf32(
    const float* __restrict__ cache_k, const float* __restrict__ cache_v)
{
    extern __shared__ float sm[];
    unsigned* Qs = (unsigned*)sm;                 // 64*132
    unsigned* Ks = Qs + 64 * 132;                 // 64*132
    float*    Sb = (float*)Ks;                    // alias, 64*68
    unsigned* Vs = Ks + 64 * 132;                 // 64*136
    float* Mi = sm + (2 * 64 * 132 + 64 * 136);   // 64
    float* Li = Mi + 64;
    float* Al = Li + 64;

    const int tid  = threadIdx.x;
    const int lane = tid & 31;
    const int wid  = tid >> 5;
    const int wm   = wid >> 1;       // 0..3
    const int wn   = wid & 1;        // 0..1
    const int lr   = lane >> 2;      // 0..7
    const int lc   = lane & 3;       // 0..3
    const int h  = blockIdx.y;
    const int qb = blockIdx.x * 64;
    const int sp = blockIdx.z;
    const float scale = 0.08838834764831845f;  // 128^-0.5

    // Load Q tile (row-major, scaled, tf32)
#pragma unroll
    for (int i = 0; i < 8; i++) {
        int t = tid + i * 256;
        int row = t >> 5;
        int d4 = (t & 31) * 4;
        float4 v = make_float4(0.f, 0.f, 0.f, 0.f);
        int qr = qb + row;
        if (qr < SEQ) v = *(const float4*)(g_q + qr * DIM + h * HD + d4);
        unsigned* qp = Qs + row * 132 + d4;
        qp[0] = cvt_tf32(v.x * scale);
        qp[1] = cvt_tf32(v.y * scale);
        qp[2] = cvt_tf32(v.z * scale);
        qp[3] = cvt_tf32(v.w * scale);
    }
    if (tid < 64) { Mi[tid] = -1e30f; Li[tid] = 0.f; }

    float oacc[8][4];
#pragma unroll
    for (int i = 0; i < 8; i++)
#pragma unroll
        for (int j = 0; j < 4; j++) oacc[i][j] = 0.f;
    __syncthreads();

    const int kbase0 = sp * (CACHE / KVSPLIT);
    for (int kb = 0; kb < KB_PER_SPLIT; kb++) {
        const int base = kbase0 + kb * 64;
        // Load K/V tiles (rolling-window substitution), cvt to tf32
#pragma unroll
        for (int i = 0; i < 8; i++) {
            int t = tid + i * 256;
            int row = t >> 5;
            int d4 = (t & 31) * 4;
            int kk = base + row;
            const float* kp;
            const float* vp;
            if (kk >= LSTART && kk < LEND) {
                int rr = kk - LSTART;
                kp = g_k + rr * DIM + h * HD;
                vp = g_v + rr * DIM + h * HD;
            } else {
                size_t off = ((size_t)kk * NH + h) * HD;
                kp = cache_k + off;
                vp = cache_v + off;
            }
            float4 kv = *(const float4*)(kp + d4);
            float4 vv = *(const float4*)(vp + d4);
            unsigned* kd = Ks + row * 132 + d4;
            kd[0] = cvt_tf32(kv.x); kd[1] = cvt_tf32(kv.y);
            kd[2] = cvt_tf32(kv.z); kd[3] = cvt_tf32(kv.w);
            unsigned* vd = Vs + row * 136 + d4;
            vd[0] = cvt_tf32(vv.x); vd[1] = cvt_tf32(vv.y);
            vd[2] = cvt_tf32(vv.z); vd[3] = cvt_tf32(vv.w);
        }
        __syncthreads();

        // S = Q @ K^T (64x64x128)
        float sacc[4][4];
#pragma unroll
        for (int i = 0; i < 4; i++)
#pragma unroll
            for (int j = 0; j < 4; j++) sacc[i][j] = 0.f;
#pragma unroll
        for (int kk = 0; kk < 16; kk++) {
            const unsigned* qp = Qs + (wm * 16 + lr) * 132 + kk * 8 + lc;
            unsigned a0 = qp[0];
            unsigned a1 = qp[8 * 132];
            unsigned a2 = qp[4];
            unsigned a3 = qp[8 * 132 + 4];
#pragma unroll
            for (int nt = 0; nt < 4; nt++) {
                const unsigned* kp = Ks + (wn * 32 + nt * 8 + lr) * 132 + kk * 8 + lc;
                mma_tf32(sacc[nt], a0, a1, a2, a3, kp[0], kp[4]);
            }
        }
        __syncthreads();  // all Ks reads done before Sb (alias) writes

        // Store S fragments to smem (fp32)
        {
            int r0 = wm * 16 + lr;
#pragma unroll
            for (int nt = 0; nt < 4; nt++) {
                int c = wn * 32 + nt * 8 + 2 * lc;
                Sb[r0 * 68 + c]     = sacc[nt][0];
                Sb[r0 * 68 + c + 1] = sacc[nt][1];
                Sb[(r0 + 8) * 68 + c]     = sacc[nt][2];
                Sb[(r0 + 8) * 68 + c + 1] = sacc[nt][3];
            }
        }
        __syncthreads();

        // Online softmax: 4 threads per row, 16 cols each
        {
            int r = tid >> 2;
            int jj = tid & 3;
            float* srow = Sb + r * 68 + jj * 16;
            float mx = srow[0];
#pragma unroll
            for (int c = 1; c < 16; c++) mx = fmaxf(mx, srow[c]);
            mx = fmaxf(mx, __shfl_xor_sync(0xffffffffu, mx, 1));
            mx = fmaxf(mx, __shfl_xor_sync(0xffffffffu, mx, 2));
            float oldm = Mi[r];
            float newm = fmaxf(oldm, mx);
            float sum = 0.f;
#pragma unroll
            for (int c = 0; c < 16; c++) {
                float p = __expf(srow[c] - newm);
                srow[c] = p;
                sum += p;
            }
            sum += __shfl_xor_sync(0xffffffffu, sum, 1);
            sum += __shfl_xor_sync(0xffffffffu, sum, 2);
            if (jj == 0) {
                Al[r] = __expf(oldm - newm);
                Mi[r] = newm;
                Li[r] = Li[r] * Al[r] + sum;
            }
        }
        __syncthreads();

        // Rescale accumulators, then O += P @ V (64x128x64)
        {
            float al0 = Al[wm * 16 + lr];
            float al1 = Al[wm * 16 + lr + 8];
#pragma unroll
            for (int nt = 0; nt < 8; nt++) {
                oacc[nt][0] *= al0; oacc[nt][1] *= al0;
                oacc[nt][2] *= al1; oacc[nt][3] *= al1;
            }
        }
#pragma unroll
        for (int kk = 0; kk < 8; kk++) {
            const float* pb = Sb + (wm * 16 + lr) * 68 + kk * 8 + lc;
            unsigned a0 = cvt_tf32(pb[0]);
            unsigned a1 = cvt_tf32(pb[8 * 68]);
            unsigned a2 = cvt_tf32(pb[4]);
            unsigned a3 = cvt_tf32(pb[8 * 68 + 4]);
#pragma unroll
            for (int nt = 0; nt < 8; nt++) {
                const unsigned* vb = Vs + (kk * 8 + lc) * 136 + wn * 64 + nt * 8 + lr;
                mma_tf32(oacc[nt], a0, a1, a2, a3, vb[0], vb[4 * 136]);
            }
        }
        __syncthreads();  // Sb/Vs reads done before next iter's K/V stores
    }

    // Store unnormalized partial + per-row stats
    {
        float* pout = g_part + (size_t)sp * SEQ * DIM;
        int r0 = qb + wm * 16 + lr;
#pragma unroll
        for (int nt = 0; nt < 8; nt++) {
            int c = h * HD + wn * 64 + nt * 8 + 2 * lc;
            if (r0 < SEQ)
                *(float2*)(pout + (size_t)r0 * DIM + c) =
                    make_float2(oacc[nt][0], oacc[nt][1]);
            if (r0 + 8 < SEQ)
                *(float2*)(pout + (size_t)(r0 + 8) * DIM + c) =
                    make_float2(oacc[nt][2], oacc[nt][3]);
        }
        if (tid < 64 && qb + tid < SEQ) {
            g_m[(sp * NH + h) * SEQ + qb + tid] = Mi[tid];
            g_l[(sp * NH + h) * SEQ + qb + tid] = Li[tid];
        }
    }
}

// ---------------------------------------------------------------------------
// Combine KV-split partials -> g_attn
// ---------------------------------------------------------------------------
__global__ __launch_bounds__(256) void combine_kernel()
{
    const int row = blockIdx.x;
    const int tid = threadIdx.x;
    const int h = tid >> 4;
    const int d0 = (tid & 15) * 8;

    float m0 = g_m[(0 * NH + h) * SEQ + row];
    float m1 = g_m[(1 * NH + h) * SEQ + row];
    float m2 = g_m[(2 * NH + h) * SEQ + row];
    float M = fmaxf(m0, fmaxf(m1, m2));
    float w0 = __expf(m0 - M);
    float w1 = __expf(m1 - M);
    float w2 = __expf(m2 - M);
    float L = w0 * g_l[(0 * NH + h) * SEQ + row] +
              w1 * g_l[(1 * NH + h) * SEQ + row] +
              w2 * g_l[(2 * NH + h) * SEQ + row];
    float inv = 1.f / L;

    size_t base = (size_t)row * DIM + h * HD + d0;
    const size_t stride = (size_t)SEQ * DIM;
#pragma unroll
    for (int half = 0; half < 2; half++) {
        float4 p0 = *(const float4*)(g_part + base + half * 4);
        float4 p1 = *(const float4*)(g_part + stride + base + half * 4);
        float4 p2 = *(const float4*)(g_part + 2 * stride + base + half * 4);
        float4 o;
        o.x = (w0 * p0.x + w1 * p1.x + w2 * p2.x) * inv;
        o.y = (w0 * p0.y + w1 * p1.y + w2 * p2.y) * inv;
        o.z = (w0 * p0.z + w1 * p1.z + w2 * p2.z) * inv;
        o.w = (w0 * p0.w + w1 * p1.w + w2 * p2.w) * inv;
        *(float4*)(g_attn + base + half * 4) = o;
    }
}

// ---------------------------------------------------------------------------
extern "C" void kernel_launch(void* const* d_in, const int* in_sizes, int n_in,
                              void* d_out, int out_size)
{
    const float* x    = (const float*)d_in[0];
    const float* q_w  = (const float*)d_in[1];
    const float* q_b  = (const float*)d_in[2];
    const float* k_w  = (const float*)d_in[3];
    const float* k_b  = (const float*)d_in[4];
    const float* v_w  = (const float*)d_in[5];
    const float* v_b  = (const float*)d_in[6];
    const float* o_w  = (const float*)d_in[7];
    const float* o_b  = (const float*)d_in[8];
    const float* nqw  = (const float*)d_in[9];
    const float* nkw  = (const float*)d_in[10];
    const float* ck   = (const float*)d_in[11];
    const float* cv   = (const float*)d_in[12];
    const float* fc   = (const float*)d_in[13];
    const float* fs   = (const float*)d_in[14];

    float *dq, *dk, *dv, *da;
    cudaGetSymbolAddress((void**)&dq, g_q);
    cudaGetSymbolAddress((void**)&dk, g_k);
    cudaGetSymbolAddress((void**)&dv, g_v);
    cudaGetSymbolAddress((void**)&da, g_attn);

    // Fused QKV projection (tf32 tensor cores)
    GemmSet sq{q_w, q_b, dq}, sk{k_w, k_b, dk}, sv{v_w, v_b, dv};
    gemm_tf32<<<dim3(16, 6, 3), 256>>>(x, sq, sk, sv, SEQ);

    // RMSNorm + RoPE (q and k, in place, fp32)
    rmsnorm_rope<<<dim3(SEQ, 2), 256>>>(nqw, nkw, fc, fs);

    // Attention (tf32 tensor cores, KV-split=3)
    const int ATTN_SMEM = (2 * 64 * 132 + 64 * 136 + 3 * 64) * 4;  // 103168
    cudaFuncSetAttribute(attn_tf32, cudaFuncAttributeMaxDynamicSharedMemorySize,
                         ATTN_SMEM);
    attn_tf32<<<dim3(12, NH, KVSPLIT), 256, ATTN_SMEM>>>(ck, cv);

    // Merge splits
    combine_kernel<<<SEQ, 256>>>();

    // Output projection -> d_out
    GemmSet so{o_w, o_b, (float*)d_out};
    gemm_tf32<<<dim3(16, 6, 1), 256>>>(da, so, so, so, SEQ);
}

// round 4
// speedup vs baseline: 4.4361x; 1.2684x over previous
#include <cuda_runtime.h>
#include <cuda_fp16.h>
#include <cstdint>

#define SEQ    720
#define DIM    2048
#define NH     16
#define HD     128
#define CACHE  11520
#define LSTART 720
#define LEND   1440
#define KVSPLIT 3
#define KB_PER_SPLIT (CACHE / KVSPLIT / 64)   // 60

#define QSTR 136   // halves per row (272 B)
#define SBSTR 68   // floats per row (272 B)
#define PSTR 72    // halves per row (144 B)

// Scratch (device globals: allocation-free rule)
__device__ float g_q[SEQ * DIM];
__device__ float g_k[SEQ * DIM];
__device__ float g_v[SEQ * DIM];
__device__ float g_attn[SEQ * DIM];
__device__ float g_part[KVSPLIT * SEQ * DIM];
__device__ float g_m[KVSPLIT * NH * SEQ];
__device__ float g_l[KVSPLIT * NH * SEQ];

// ---------------------------------------------------------------------------
// helpers
// ---------------------------------------------------------------------------
__device__ __forceinline__ unsigned cvt_tf32(float x) {
    unsigned r;
    asm("cvt.rna.tf32.f32 %0, %1;" : "=r"(r) : "f"(x));
    return r;
}

__device__ __forceinline__ void mma_tf32(float* c, unsigned a0, unsigned a1,
                                         unsigned a2, unsigned a3,
                                         unsigned b0, unsigned b1) {
    asm volatile(
        "mma.sync.aligned.m16n8k8.row.col.f32.tf32.tf32.f32 "
        "{%0,%1,%2,%3},{%4,%5,%6,%7},{%8,%9},{%0,%1,%2,%3};\n"
        : "+f"(c[0]), "+f"(c[1]), "+f"(c[2]), "+f"(c[3])
        : "r"(a0), "r"(a1), "r"(a2), "r"(a3), "r"(b0), "r"(b1));
}

__device__ __forceinline__ void mma_f16(float* c, uint32_t a0, uint32_t a1,
                                        uint32_t a2, uint32_t a3,
                                        uint32_t b0, uint32_t b1) {
    asm volatile(
        "mma.sync.aligned.m16n8k16.row.col.f32.f16.f16.f32 "
        "{%0,%1,%2,%3},{%4,%5,%6,%7},{%8,%9},{%0,%1,%2,%3};\n"
        : "+f"(c[0]), "+f"(c[1]), "+f"(c[2]), "+f"(c[3])
        : "r"(a0), "r"(a1), "r"(a2), "r"(a3), "r"(b0), "r"(b1));
}

__device__ __forceinline__ uint32_t sm_u32(const void* p) {
    uint32_t a;
    asm("{ .reg .u64 t; cvta.to.shared.u64 t, %1; cvt.u32.u64 %0, t; }"
        : "=r"(a) : "l"(p));
    return a;
}

#define LDSM4(r0_, r1_, r2_, r3_, a_) \
    asm volatile("ldmatrix.sync.aligned.m8n8.x4.shared.b16 {%0,%1,%2,%3}, [%4];" \
                 : "=r"(r0_), "=r"(r1_), "=r"(r2_), "=r"(r3_) : "r"(a_))
#define LDSM2(r0_, r1_, a_) \
    asm volatile("ldmatrix.sync.aligned.m8n8.x2.shared.b16 {%0,%1}, [%2];" \
                 : "=r"(r0_), "=r"(r1_) : "r"(a_))
#define LDSM2T(r0_, r1_, a_) \
    asm volatile("ldmatrix.sync.aligned.m8n8.x2.trans.shared.b16 {%0,%1}, [%2];" \
                 : "=r"(r0_), "=r"(r1_) : "r"(a_))

// ---------------------------------------------------------------------------
// GEMM (NT, tf32 mma.sync): C[m,n] = bias[n] + sum_k A[m,k] * B[n,k]
// (unchanged from R2 — known good)
// ---------------------------------------------------------------------------
struct GemmSet {
    const float* B;
    const float* bias;
    float* C;
};

__global__ __launch_bounds__(256, 2) void gemm_tf32(
    const float* __restrict__ A, GemmSet s0, GemmSet s1, GemmSet s2, int M)
{
    GemmSet s = (blockIdx.z == 0) ? s0 : ((blockIdx.z == 1) ? s1 : s2);

    __shared__ unsigned As[128 * 20];
    __shared__ unsigned Bs[128 * 20];

    const int tid  = threadIdx.x;
    const int lane = tid & 31;
    const int wid  = tid >> 5;
    const int wm   = wid >> 2;
    const int wn   = wid & 3;
    const int lr   = lane >> 2;
    const int lc   = lane & 3;
    const int bm = blockIdx.y * 128;
    const int bn = blockIdx.x * 128;

    const int r  = tid >> 2;
    const int c4 = (tid & 3) * 4;

    float acc[4][4][4];
#pragma unroll
    for (int i = 0; i < 4; i++)
#pragma unroll
        for (int j = 0; j < 4; j++)
#pragma unroll
            for (int q = 0; q < 4; q++) acc[i][j][q] = 0.f;

    const bool a0ok = (bm + r) < M;
    const bool a1ok = (bm + r + 64) < M;
    const float* Ap0 = A + (size_t)(bm + r) * 2048 + c4;
    const float* Ap1 = A + (size_t)(bm + r + 64) * 2048 + c4;
    const float* Bp0 = s.B + (size_t)(bn + r) * 2048 + c4;
    const float* Bp1 = s.B + (size_t)(bn + r + 64) * 2048 + c4;

    float4 ra0 = a0ok ? *(const float4*)Ap0 : make_float4(0, 0, 0, 0);
    float4 ra1 = a1ok ? *(const float4*)Ap1 : make_float4(0, 0, 0, 0);
    float4 rb0 = *(const float4*)Bp0;
    float4 rb1 = *(const float4*)Bp1;

    for (int k0 = 0; k0 < 2048; k0 += 16) {
        unsigned* as0 = As + r * 20 + c4;
        as0[0] = cvt_tf32(ra0.x); as0[1] = cvt_tf32(ra0.y);
        as0[2] = cvt_tf32(ra0.z); as0[3] = cvt_tf32(ra0.w);
        unsigned* as1 = As + (r + 64) * 20 + c4;
        as1[0] = cvt_tf32(ra1.x); as1[1] = cvt_tf32(ra1.y);
        as1[2] = cvt_tf32(ra1.z); as1[3] = cvt_tf32(ra1.w);
        unsigned* bs0 = Bs + r * 20 + c4;
        bs0[0] = cvt_tf32(rb0.x); bs0[1] = cvt_tf32(rb0.y);
        bs0[2] = cvt_tf32(rb0.z); bs0[3] = cvt_tf32(rb0.w);
        unsigned* bs1 = Bs + (r + 64) * 20 + c4;
        bs1[0] = cvt_tf32(rb1.x); bs1[1] = cvt_tf32(rb1.y);
        bs1[2] = cvt_tf32(rb1.z); bs1[3] = cvt_tf32(rb1.w);
        __syncthreads();

        if (k0 + 16 < 2048) {
            ra0 = a0ok ? *(const float4*)(Ap0 + k0 + 16) : make_float4(0, 0, 0, 0);
            ra1 = a1ok ? *(const float4*)(Ap1 + k0 + 16) : make_float4(0, 0, 0, 0);
            rb0 = *(const float4*)(Bp0 + k0 + 16);
            rb1 = *(const float4*)(Bp1 + k0 + 16);
        }

#pragma unroll
        for (int kk = 0; kk < 2; kk++) {
            unsigned af[4][4];
            unsigned bf[4][2];
#pragma unroll
            for (int mt = 0; mt < 4; mt++) {
                const unsigned* ab = As + (wm * 64 + mt * 16 + lr) * 20 + kk * 8 + lc;
                af[mt][0] = ab[0];
                af[mt][1] = ab[8 * 20];
                af[mt][2] = ab[4];
                af[mt][3] = ab[8 * 20 + 4];
            }
#pragma unroll
            for (int nt = 0; nt < 4; nt++) {
                const unsigned* bb = Bs + (wn * 32 + nt * 8 + lr) * 20 + kk * 8 + lc;
                bf[nt][0] = bb[0];
                bf[nt][1] = bb[4];
            }
#pragma unroll
            for (int mt = 0; mt < 4; mt++)
#pragma unroll
                for (int nt = 0; nt < 4; nt++)
                    mma_tf32(acc[mt][nt], af[mt][0], af[mt][1], af[mt][2], af[mt][3],
                             bf[nt][0], bf[nt][1]);
        }
        __syncthreads();
    }

#pragma unroll
    for (int mt = 0; mt < 4; mt++) {
        int row = bm + wm * 64 + mt * 16 + lr;
#pragma unroll
        for (int nt = 0; nt < 4; nt++) {
            int col = bn + wn * 32 + nt * 8 + 2 * lc;
            float b0v = s.bias[col], b1v = s.bias[col + 1];
            if (row < M) {
                float2 o = make_float2(acc[mt][nt][0] + b0v, acc[mt][nt][1] + b1v);
                *(float2*)(s.C + (size_t)row * 2048 + col) = o;
            }
            if (row + 8 < M) {
                float2 o = make_float2(acc[mt][nt][2] + b0v, acc[mt][nt][3] + b1v);
                *(float2*)(s.C + (size_t)(row + 8) * 2048 + col) = o;
            }
        }
    }
}

// ---------------------------------------------------------------------------
// RMSNorm + RoPE, in place on g_q (blockIdx.y=0) / g_k (blockIdx.y=1)
// ---------------------------------------------------------------------------
__global__ __launch_bounds__(256) void rmsnorm_rope(
    const float* __restrict__ wq, const float* __restrict__ wk,
    const float* __restrict__ fc, const float* __restrict__ fs)
{
    const int s = blockIdx.x;
    float* row = (blockIdx.y == 0 ? g_q : g_k) + s * DIM;
    const float* w = (blockIdx.y == 0) ? wq : wk;
    const int tid = threadIdx.x;

    float4 v0 = ((const float4*)row)[tid * 2];
    float4 v1 = ((const float4*)row)[tid * 2 + 1];
    float ss = v0.x * v0.x + v0.y * v0.y + v0.z * v0.z + v0.w * v0.w +
               v1.x * v1.x + v1.y * v1.y + v1.z * v1.z + v1.w * v1.w;
#pragma unroll
    for (int o = 16; o > 0; o >>= 1) ss += __shfl_xor_sync(0xffffffffu, ss, o);

    __shared__ float red[8];
    __shared__ float stot;
    if ((tid & 31) == 0) red[tid >> 5] = ss;
    __syncthreads();
    if (tid == 0) {
        float t = 0.f;
#pragma unroll
        for (int i = 0; i < 8; i++) t += red[i];
        stot = t;
    }
    __syncthreads();
    const float r = rsqrtf(stot * (1.0f / DIM) + 1e-6f);

    const int e = tid * 8;
    float xv[8] = {v0.x, v0.y, v0.z, v0.w, v1.x, v1.y, v1.z, v1.w};
    float ov[8];
#pragma unroll
    for (int i = 0; i < 4; i++) {
        int e0 = e + 2 * i;
        int j = (e0 & 127) >> 1;
        float c = fc[s * 64 + j];
        float sn = fs[s * 64 + j];
        float a = xv[2 * i] * r * w[e0];
        float b = xv[2 * i + 1] * r * w[e0 + 1];
        ov[2 * i] = a * c - b * sn;
        ov[2 * i + 1] = a * sn + b * c;
    }
    ((float4*)row)[tid * 2] = make_float4(ov[0], ov[1], ov[2], ov[3]);
    ((float4*)row)[tid * 2 + 1] = make_float4(ov[4], ov[5], ov[6], ov[7]);
}

// ---------------------------------------------------------------------------
// Flash attention, fp16 m16n8k16 + ldmatrix, online softmax, KV-split=3.
// Block = (64-query tile, head, split). 8 warps: wm=wid>>1 (m16), wn=wid&1.
// smem: Qh 64x136h | Kh 64x136h (Sb fp32 64x68 aliases) | Vh 64x136h |
//       Ph 64x72h | Mi/Li/Al 64 f32  = 62208 B -> 2 blocks/SM
// ---------------------------------------------------------------------------
__global__ __launch_bounds__(256, 2) void attn_fp16(
    const float* __restrict__ cache_k, const float* __restrict__ cache_v)
{
    extern __shared__ char smc[];
    __half* Qh = (__half*)smc;            // 64*136
    __half* Kh = Qh + 64 * QSTR;          // 64*136
    float*  Sb = (float*)Kh;              // alias: 64*68 f32 == same bytes
    __half* Vh = Kh + 64 * QSTR;          // 64*136
    __half* Ph = Vh + 64 * QSTR;          // 64*72
    float*  Mi = (float*)(Ph + 64 * PSTR);
    float*  Li = Mi + 64;
    float*  Al = Li + 64;

    const uint32_t uQ = sm_u32(smc);
    const uint32_t uK = uQ + 64 * QSTR * 2;
    const uint32_t uV = uK + 64 * QSTR * 2;
    const uint32_t uP = uV + 64 * QSTR * 2;

    const int tid  = threadIdx.x;
    const int lane = tid & 31;
    const int wid  = tid >> 5;
    const int wm   = wid >> 1;       // 0..3 (query 16-row tile)
    const int wn   = wid & 1;        // 0..1
    const int lr   = lane >> 2;      // 0..7
    const int lc   = lane & 3;       // 0..3
    const int h  = blockIdx.y;
    const int qb = blockIdx.x * 64;
    const int sp = blockIdx.z;
    const float scale = 0.08838834764831845f;  // 128^-0.5

    // ldmatrix lane address components (bytes)
    const uint32_t a_row = (uint32_t)(lane & 15);       // A frags (x4)
    const uint32_t a_coff = (uint32_t)((lane >> 4) * 8) * 2;
    const uint32_t b_row = (uint32_t)(lane & 7);        // B frags (x2)
    const uint32_t b_coff = (uint32_t)(((lane >> 3) & 1) * 8) * 2;

    // Load Q tile (scaled, fp16)
#pragma unroll
    for (int i = 0; i < 8; i++) {
        int t = tid + i * 256;
        int row = t >> 5;
        int d4 = (t & 31) * 4;
        float4 v = make_float4(0.f, 0.f, 0.f, 0.f);
        int qr = qb + row;
        if (qr < SEQ) v = *(const float4*)(g_q + qr * DIM + h * HD + d4);
        union { __half2 hh[2]; uint2 u; } pk;
        pk.hh[0] = __floats2half2_rn(v.x * scale, v.y * scale);
        pk.hh[1] = __floats2half2_rn(v.z * scale, v.w * scale);
        *(uint2*)&Qh[row * QSTR + d4] = pk.u;
    }
    if (tid < 64) { Mi[tid] = -1e30f; Li[tid] = 0.f; }

    float oacc[8][4];
#pragma unroll
    for (int i = 0; i < 8; i++)
#pragma unroll
        for (int j = 0; j < 4; j++) oacc[i][j] = 0.f;
    __syncthreads();

    const int kbase0 = sp * (CACHE / KVSPLIT);
    for (int kb = 0; kb < KB_PER_SPLIT; kb++) {
        const int base = kbase0 + kb * 64;
        // Load K/V tiles (rolling-window substitution), fp16
#pragma unroll
        for (int i = 0; i < 8; i++) {
            int t = tid + i * 256;
            int row = t >> 5;
            int d4 = (t & 31) * 4;
            int kk = base + row;
            const float* kp;
            const float* vp;
            if (kk >= LSTART && kk < LEND) {
                int rr = kk - LSTART;
                kp = g_k + rr * DIM + h * HD;
                vp = g_v + rr * DIM + h * HD;
            } else {
                size_t off = ((size_t)kk * NH + h) * HD;
                kp = cache_k + off;
                vp = cache_v + off;
            }
            float4 kv = *(const float4*)(kp + d4);
            float4 vv = *(const float4*)(vp + d4);
            union { __half2 hh[2]; uint2 u; } pk;
            pk.hh[0] = __floats2half2_rn(kv.x, kv.y);
            pk.hh[1] = __floats2half2_rn(kv.z, kv.w);
            *(uint2*)&Kh[row * QSTR + d4] = pk.u;
            pk.hh[0] = __floats2half2_rn(vv.x, vv.y);
            pk.hh[1] = __floats2half2_rn(vv.z, vv.w);
            *(uint2*)&Vh[row * QSTR + d4] = pk.u;
        }
        __syncthreads();

        // S = Q @ K^T (64x64x128), fp16 m16n8k16
        float sacc[4][4];
#pragma unroll
        for (int i = 0; i < 4; i++)
#pragma unroll
            for (int j = 0; j < 4; j++) sacc[i][j] = 0.f;
#pragma unroll
        for (int kk = 0; kk < 8; kk++) {
            uint32_t a0, a1, a2, a3;
            uint32_t aaddr = uQ + ((wm * 16 + a_row) * QSTR + kk * 16) * 2 + a_coff;
            LDSM4(a0, a1, a2, a3, aaddr);
#pragma unroll
            for (int nt = 0; nt < 4; nt++) {
                uint32_t b0, b1;
                uint32_t baddr =
                    uK + ((wn * 32 + nt * 8 + b_row) * QSTR + kk * 16) * 2 + b_coff;
                LDSM2(b0, b1, baddr);
                mma_f16(sacc[nt], a0, a1, a2, a3, b0, b1);
            }
        }
        __syncthreads();  // Kh reads done before Sb (alias) writes

        // Store S fragments to smem (fp32)
        {
            int r0 = wm * 16 + lr;
#pragma unroll
            for (int nt = 0; nt < 4; nt++) {
                int c = wn * 32 + nt * 8 + 2 * lc;
                Sb[r0 * SBSTR + c]     = sacc[nt][0];
                Sb[r0 * SBSTR + c + 1] = sacc[nt][1];
                Sb[(r0 + 8) * SBSTR + c]     = sacc[nt][2];
                Sb[(r0 + 8) * SBSTR + c + 1] = sacc[nt][3];
            }
        }
        __syncthreads();

        // Online softmax: 4 threads per row, 16 cols each; write P as fp16
        {
            int r = tid >> 2;
            int jj = tid & 3;
            float* srow = Sb + r * SBSTR + jj * 16;
            __half2* prow = (__half2*)(Ph + r * PSTR + jj * 16);
            float mx = srow[0];
#pragma unroll
            for (int c = 1; c < 16; c++) mx = fmaxf(mx, srow[c]);
            mx = fmaxf(mx, __shfl_xor_sync(0xffffffffu, mx, 1));
            mx = fmaxf(mx, __shfl_xor_sync(0xffffffffu, mx, 2));
            float oldm = Mi[r];
            float newm = fmaxf(oldm, mx);
            float sum = 0.f;
#pragma unroll
            for (int c = 0; c < 8; c++) {
                float p0 = __expf(srow[2 * c] - newm);
                float p1 = __expf(srow[2 * c + 1] - newm);
                sum += p0 + p1;
                prow[c] = __floats2half2_rn(p0, p1);
            }
            sum += __shfl_xor_sync(0xffffffffu, sum, 1);
            sum += __shfl_xor_sync(0xffffffffu, sum, 2);
            if (jj == 0) {
                Al[r] = __expf(oldm - newm);
                Mi[r] = newm;
                Li[r] = Li[r] * Al[r] + sum;
            }
        }
        __syncthreads();

        // Rescale accumulators, then O += P @ V (64x128x64)
        {
            float al0 = Al[wm * 16 + lr];
            float al1 = Al[wm * 16 + lr + 8];
#pragma unroll
            for (int nt = 0; nt < 8; nt++) {
                oacc[nt][0] *= al0; oacc[nt][1] *= al0;
                oacc[nt][2] *= al1; oacc[nt][3] *= al1;
            }
        }
#pragma unroll
        for (int kk = 0; kk < 4; kk++) {
            uint32_t a0, a1, a2, a3;
            uint32_t paddr = uP + ((wm * 16 + a_row) * PSTR + kk * 16) * 2 + a_coff;
            LDSM4(a0, a1, a2, a3, paddr);
#pragma unroll
            for (int nt = 0; nt < 8; nt++) {
                uint32_t b0, b1;
                uint32_t vaddr =
                    uV + ((kk * 16 + (lane & 15)) * QSTR + wn * 64 + nt * 8) * 2;
                LDSM2T(b0, b1, vaddr);
                mma_f16(oacc[nt], a0, a1, a2, a3, b0, b1);
            }
        }
        __syncthreads();  // Vh/Ph reads done before next iter's stores
    }

    // Store unnormalized partial + per-row stats
    {
        float* pout = g_part + (size_t)sp * SEQ * DIM;
        int r0 = qb + wm * 16 + lr;
#pragma unroll
        for (int nt = 0; nt < 8; nt++) {
            int c = h * HD + wn * 64 + nt * 8 + 2 * lc;
            if (r0 < SEQ)
                *(float2*)(pout + (size_t)r0 * DIM + c) =
                    make_float2(oacc[nt][0], oacc[nt][1]);
            if (r0 + 8 < SEQ)
                *(float2*)(pout + (size_t)(r0 + 8) * DIM + c) =
                    make_float2(oacc[nt][2], oacc[nt][3]);
        }
        if (tid < 64 && qb + tid < SEQ) {
            g_m[(sp * NH + h) * SEQ + qb + tid] = Mi[tid];
            g_l[(sp * NH + h) * SEQ + qb + tid] = Li[tid];
        }
    }
}

// ---------------------------------------------------------------------------
// Combine KV-split partials -> g_attn
// ---------------------------------------------------------------------------
__global__ __launch_bounds__(256) void combine_kernel()
{
    const int row = blockIdx.x;
    const int tid = threadIdx.x;
    const int h = tid >> 4;
    const int d0 = (tid & 15) * 8;

    float m0 = g_m[(0 * NH + h) * SEQ + row];
    float m1 = g_m[(1 * NH + h) * SEQ + row];
    float m2 = g_m[(2 * NH + h) * SEQ + row];
    float M = fmaxf(m0, fmaxf(m1, m2));
    float w0 = __expf(m0 - M);
    float w1 = __expf(m1 - M);
    float w2 = __expf(m2 - M);
    float L = w0 * g_l[(0 * NH + h) * SEQ + row] +
              w1 * g_l[(1 * NH + h) * SEQ + row] +
              w2 * g_l[(2 * NH + h) * SEQ + row];
    float inv = 1.f / L;

    size_t base = (size_t)row * DIM + h * HD + d0;
    const size_t stride = (size_t)SEQ * DIM;
#pragma unroll
    for (int half = 0; half < 2; half++) {
        float4 p0 = *(const float4*)(g_part + base + half * 4);
        float4 p1 = *(const float4*)(g_part + stride + base + half * 4);
        float4 p2 = *(const float4*)(g_part + 2 * stride + base + half * 4);
        float4 o;
        o.x = (w0 * p0.x + w1 * p1.x + w2 * p2.x) * inv;
        o.y = (w0 * p0.y + w1 * p1.y + w2 * p2.y) * inv;
        o.z = (w0 * p0.z + w1 * p1.z + w2 * p2.z) * inv;
        o.w = (w0 * p0.w + w1 * p1.w + w2 * p2.w) * inv;
        *(float4*)(g_attn + base + half * 4) = o;
    }
}

// ---------------------------------------------------------------------------
extern "C" void kernel_launch(void* const* d_in, const int* in_sizes, int n_in,
                              void* d_out, int out_size)
{
    const float* x    = (const float*)d_in[0];
    const float* q_w  = (const float*)d_in[1];
    const float* q_b  = (const float*)d_in[2];
    const float* k_w  = (const float*)d_in[3];
    const float* k_b  = (const float*)d_in[4];
    const float* v_w  = (const float*)d_in[5];
    const float* v_b  = (const float*)d_in[6];
    const float* o_w  = (const float*)d_in[7];
    const float* o_b  = (const float*)d_in[8];
    const float* nqw  = (const float*)d_in[9];
    const float* nkw  = (const float*)d_in[10];
    const float* ck   = (const float*)d_in[11];
    const float* cv   = (const float*)d_in[12];
    const float* fc   = (const float*)d_in[13];
    const float* fs   = (const float*)d_in[14];

    float *dq, *dk, *dv, *da;
    cudaGetSymbolAddress((void**)&dq, g_q);
    cudaGetSymbolAddress((void**)&dk, g_k);
    cudaGetSymbolAddress((void**)&dv, g_v);
    cudaGetSymbolAddress((void**)&da, g_attn);

    // Fused QKV projection (tf32 mma.sync)
    GemmSet sq{q_w, q_b, dq}, sk{k_w, k_b, dk}, sv{v_w, v_b, dv};
    gemm_tf32<<<dim3(16, 6, 3), 256>>>(x, sq, sk, sv, SEQ);

    // RMSNorm + RoPE (q and k, in place, fp32)
    rmsnorm_rope<<<dim3(SEQ, 2), 256>>>(nqw, nkw, fc, fs);

    // Attention (fp16 ldmatrix + m16n8k16, KV-split=3)
    const int ATTN_SMEM = 3 * 64 * QSTR * 2 + 64 * PSTR * 2 + 3 * 64 * 4; // 62208
    cudaFuncSetAttribute(attn_fp16, cudaFuncAttributeMaxDynamicSharedMemorySize,
                         ATTN_SMEM);
    attn_fp16<<<dim3(12, NH, KVSPLIT), 256, ATTN_SMEM>>>(ck, cv);

    // Merge splits
    combine_kernel<<<SEQ, 256>>>();

    // Output projection -> d_out (tf32 mma.sync)
    GemmSet so{o_w, o_b, (float*)d_out};
    gemm_tf32<<<dim3(16, 6, 1), 256>>>(da, so, so, so, SEQ);
}

// round 5
// speedup vs baseline: 5.3769x; 1.2121x over previous
#include <cuda_runtime.h>
#include <cuda_fp16.h>
#include <cstdint>

#define SEQ    720
#define DIM    2048
#define NH     16
#define HD     128
#define CACHE  11520
#define LSTART 720
#define LEND   1440
#define KVSPLIT 3
#define KB_PER_SPLIT (CACHE / KVSPLIT / 64)   // 60

#define QSTR 136   // halves per row (272 B)
#define SBSTR 68   // floats per row (272 B)
#define PSTR 72    // halves per row (144 B)
#define GSTR 40    // gemm smem halves per row (80 B)

// Scratch (device globals: allocation-free rule)
__device__ float g_q[SEQ * DIM];
__device__ float g_k[SEQ * DIM];
__device__ float g_v[SEQ * DIM];
__device__ float g_attn[SEQ * DIM];
__device__ float g_part[KVSPLIT * SEQ * DIM];
__device__ float g_m[KVSPLIT * NH * SEQ];
__device__ float g_l[KVSPLIT * NH * SEQ];

// ---------------------------------------------------------------------------
// helpers
// ---------------------------------------------------------------------------
__device__ __forceinline__ void mma_f16(float* c, uint32_t a0, uint32_t a1,
                                        uint32_t a2, uint32_t a3,
                                        uint32_t b0, uint32_t b1) {
    asm volatile(
        "mma.sync.aligned.m16n8k16.row.col.f32.f16.f16.f32 "
        "{%0,%1,%2,%3},{%4,%5,%6,%7},{%8,%9},{%0,%1,%2,%3};\n"
        : "+f"(c[0]), "+f"(c[1]), "+f"(c[2]), "+f"(c[3])
        : "r"(a0), "r"(a1), "r"(a2), "r"(a3), "r"(b0), "r"(b1));
}

__device__ __forceinline__ uint32_t sm_u32(const void* p) {
    uint32_t a;
    asm("{ .reg .u64 t; cvta.to.shared.u64 t, %1; cvt.u32.u64 %0, t; }"
        : "=r"(a) : "l"(p));
    return a;
}

#define LDSM4(r0_, r1_, r2_, r3_, a_) \
    asm volatile("ldmatrix.sync.aligned.m8n8.x4.shared.b16 {%0,%1,%2,%3}, [%4];" \
                 : "=r"(r0_), "=r"(r1_), "=r"(r2_), "=r"(r3_) : "r"(a_))
#define LDSM2(r0_, r1_, a_) \
    asm volatile("ldmatrix.sync.aligned.m8n8.x2.shared.b16 {%0,%1}, [%2];" \
                 : "=r"(r0_), "=r"(r1_) : "r"(a_))
#define LDSM2T(r0_, r1_, a_) \
    asm volatile("ldmatrix.sync.aligned.m8n8.x2.trans.shared.b16 {%0,%1}, [%2];" \
                 : "=r"(r0_), "=r"(r1_) : "r"(a_))

__device__ __forceinline__ uint2 pack_h4(float x, float y, float z, float w) {
    union { __half2 hh[2]; uint2 u; } pk;
    pk.hh[0] = __floats2half2_rn(x, y);
    pk.hh[1] = __floats2half2_rn(z, w);
    return pk.u;
}

// ---------------------------------------------------------------------------
// GEMM (NT, fp16 m16n8k16 + ldmatrix): C[m,n] = bias[n] + sum_k A[m,k]*B[n,k]
// BM=BN=128, BK=32, 256 threads (8 warps, 2x4), warp tile 64x32.
// N = K = 2048 fixed. gridDim.z selects the (B, bias, C) set (fused QKV).
// ---------------------------------------------------------------------------
struct GemmSet {
    const float* B;
    const float* bias;
    float* C;
};

__global__ __launch_bounds__(256, 2) void gemm_f16(
    const float* __restrict__ A, GemmSet s0, GemmSet s1, GemmSet s2, int M)
{
    GemmSet s = (blockIdx.z == 0) ? s0 : ((blockIdx.z == 1) ? s1 : s2);

    __shared__ __half Ah[128 * GSTR];
    __shared__ __half Bh[128 * GSTR];
    const uint32_t uA = sm_u32(Ah);
    const uint32_t uB = sm_u32(Bh);

    const int tid  = threadIdx.x;
    const int lane = tid & 31;
    const int wid  = tid >> 5;
    const int wm   = wid >> 2;       // 0..1
    const int wn   = wid & 3;        // 0..3
    const int lr   = lane >> 2;      // 0..7
    const int lc   = lane & 3;       // 0..3
    const int bm = blockIdx.y * 128;
    const int bn = blockIdx.x * 128;

    // ldmatrix lane address components (bytes)
    const uint32_t a_row = (uint32_t)(lane & 15);
    const uint32_t a_coff = (uint32_t)((lane >> 4) * 8) * 2;
    const uint32_t b_row = (uint32_t)(lane & 7);
    const uint32_t b_coff = (uint32_t)(((lane >> 3) & 1) * 8) * 2;

    float acc[4][4][4];
#pragma unroll
    for (int i = 0; i < 4; i++)
#pragma unroll
        for (int j = 0; j < 4; j++)
#pragma unroll
            for (int q = 0; q < 4; q++) acc[i][j][q] = 0.f;

    // load mapping: t = tid + i*256 (i<4): row = t>>3 (0..127), col = (t&7)*4
    const int lrow = tid >> 3;
    const int lcol = (tid & 7) * 4;
    bool aok[4];
    const float* Ap[4];
    const float* Bp[4];
#pragma unroll
    for (int i = 0; i < 4; i++) {
        int row = lrow + i * 32;
        aok[i] = (bm + row) < M;
        Ap[i] = A + (size_t)(bm + row) * 2048 + lcol;
        Bp[i] = s.B + (size_t)(bn + row) * 2048 + lcol;
    }

    float4 ra[4], rb[4];
#pragma unroll
    for (int i = 0; i < 4; i++) {
        ra[i] = aok[i] ? *(const float4*)Ap[i] : make_float4(0, 0, 0, 0);
        rb[i] = *(const float4*)Bp[i];
    }

    for (int k0 = 0; k0 < 2048; k0 += 32) {
        // store prefetched chunk (cvt fp16)
#pragma unroll
        for (int i = 0; i < 4; i++) {
            int row = lrow + i * 32;
            *(uint2*)&Ah[row * GSTR + lcol] = pack_h4(ra[i].x, ra[i].y, ra[i].z, ra[i].w);
            *(uint2*)&Bh[row * GSTR + lcol] = pack_h4(rb[i].x, rb[i].y, rb[i].z, rb[i].w);
        }
        __syncthreads();

        // prefetch next chunk
        if (k0 + 32 < 2048) {
#pragma unroll
            for (int i = 0; i < 4; i++) {
                ra[i] = aok[i] ? *(const float4*)(Ap[i] + k0 + 32)
                               : make_float4(0, 0, 0, 0);
                rb[i] = *(const float4*)(Bp[i] + k0 + 32);
            }
        }

#pragma unroll
        for (int kk = 0; kk < 2; kk++) {
            uint32_t af[4][4];
            uint32_t bf[4][2];
#pragma unroll
            for (int mt = 0; mt < 4; mt++) {
                uint32_t aaddr =
                    uA + ((wm * 64 + mt * 16 + a_row) * GSTR + kk * 16) * 2 + a_coff;
                LDSM4(af[mt][0], af[mt][1], af[mt][2], af[mt][3], aaddr);
            }
#pragma unroll
            for (int nt = 0; nt < 4; nt++) {
                uint32_t baddr =
                    uB + ((wn * 32 + nt * 8 + b_row) * GSTR + kk * 16) * 2 + b_coff;
                LDSM2(bf[nt][0], bf[nt][1], baddr);
            }
#pragma unroll
            for (int mt = 0; mt < 4; mt++)
#pragma unroll
                for (int nt = 0; nt < 4; nt++)
                    mma_f16(acc[mt][nt], af[mt][0], af[mt][1], af[mt][2], af[mt][3],
                            bf[nt][0], bf[nt][1]);
        }
        __syncthreads();
    }

    // epilogue: bias add + store (fp32)
#pragma unroll
    for (int mt = 0; mt < 4; mt++) {
        int row = bm + wm * 64 + mt * 16 + lr;
#pragma unroll
        for (int nt = 0; nt < 4; nt++) {
            int col = bn + wn * 32 + nt * 8 + 2 * lc;
            float b0v = s.bias[col], b1v = s.bias[col + 1];
            if (row < M) {
                float2 o = make_float2(acc[mt][nt][0] + b0v, acc[mt][nt][1] + b1v);
                *(float2*)(s.C + (size_t)row * 2048 + col) = o;
            }
            if (row + 8 < M) {
                float2 o = make_float2(acc[mt][nt][2] + b0v, acc[mt][nt][3] + b1v);
                *(float2*)(s.C + (size_t)(row + 8) * 2048 + col) = o;
            }
        }
    }
}

// ---------------------------------------------------------------------------
// RMSNorm + RoPE, in place on g_q (blockIdx.y=0) / g_k (blockIdx.y=1)
// ---------------------------------------------------------------------------
__global__ __launch_bounds__(256) void rmsnorm_rope(
    const float* __restrict__ wq, const float* __restrict__ wk,
    const float* __restrict__ fc, const float* __restrict__ fs)
{
    const int s = blockIdx.x;
    float* row = (blockIdx.y == 0 ? g_q : g_k) + s * DIM;
    const float* w = (blockIdx.y == 0) ? wq : wk;
    const int tid = threadIdx.x;

    float4 v0 = ((const float4*)row)[tid * 2];
    float4 v1 = ((const float4*)row)[tid * 2 + 1];
    float ss = v0.x * v0.x + v0.y * v0.y + v0.z * v0.z + v0.w * v0.w +
               v1.x * v1.x + v1.y * v1.y + v1.z * v1.z + v1.w * v1.w;
#pragma unroll
    for (int o = 16; o > 0; o >>= 1) ss += __shfl_xor_sync(0xffffffffu, ss, o);

    __shared__ float red[8];
    __shared__ float stot;
    if ((tid & 31) == 0) red[tid >> 5] = ss;
    __syncthreads();
    if (tid == 0) {
        float t = 0.f;
#pragma unroll
        for (int i = 0; i < 8; i++) t += red[i];
        stot = t;
    }
    __syncthreads();
    const float r = rsqrtf(stot * (1.0f / DIM) + 1e-6f);

    const int e = tid * 8;
    float xv[8] = {v0.x, v0.y, v0.z, v0.w, v1.x, v1.y, v1.z, v1.w};
    float ov[8];
#pragma unroll
    for (int i = 0; i < 4; i++) {
        int e0 = e + 2 * i;
        int j = (e0 & 127) >> 1;
        float c = fc[s * 64 + j];
        float sn = fs[s * 64 + j];
        float a = xv[2 * i] * r * w[e0];
        float b = xv[2 * i + 1] * r * w[e0 + 1];
        ov[2 * i] = a * c - b * sn;
        ov[2 * i + 1] = a * sn + b * c;
    }
    ((float4*)row)[tid * 2] = make_float4(ov[0], ov[1], ov[2], ov[3]);
    ((float4*)row)[tid * 2 + 1] = make_float4(ov[4], ov[5], ov[6], ov[7]);
}

// ---------------------------------------------------------------------------
// Flash attention, fp16 m16n8k16 + ldmatrix, online softmax, KV-split=3.
// (unchanged from R4 — known good)
// ---------------------------------------------------------------------------
__global__ __launch_bounds__(256, 2) void attn_fp16(
    const float* __restrict__ cache_k, const float* __restrict__ cache_v)
{
    extern __shared__ char smc[];
    __half* Qh = (__half*)smc;            // 64*136
    __half* Kh = Qh + 64 * QSTR;          // 64*136
    float*  Sb = (float*)Kh;              // alias: 64*68 f32 == same bytes
    __half* Vh = Kh + 64 * QSTR;          // 64*136
    __half* Ph = Vh + 64 * QSTR;          // 64*72
    float*  Mi = (float*)(Ph + 64 * PSTR);
    float*  Li = Mi + 64;
    float*  Al = Li + 64;

    const uint32_t uQ = sm_u32(smc);
    const uint32_t uK = uQ + 64 * QSTR * 2;
    const uint32_t uV = uK + 64 * QSTR * 2;
    const uint32_t uP = uV + 64 * QSTR * 2;

    const int tid  = threadIdx.x;
    const int lane = tid & 31;
    const int wid  = tid >> 5;
    const int wm   = wid >> 1;       // 0..3 (query 16-row tile)
    const int wn   = wid & 1;        // 0..1
    const int lr   = lane >> 2;      // 0..7
    const int lc   = lane & 3;       // 0..3
    const int h  = blockIdx.y;
    const int qb = blockIdx.x * 64;
    const int sp = blockIdx.z;
    const float scale = 0.08838834764831845f;  // 128^-0.5

    const uint32_t a_row = (uint32_t)(lane & 15);
    const uint32_t a_coff = (uint32_t)((lane >> 4) * 8) * 2;
    const uint32_t b_row = (uint32_t)(lane & 7);
    const uint32_t b_coff = (uint32_t)(((lane >> 3) & 1) * 8) * 2;

    // Load Q tile (scaled, fp16)
#pragma unroll
    for (int i = 0; i < 8; i++) {
        int t = tid + i * 256;
        int row = t >> 5;
        int d4 = (t & 31) * 4;
        float4 v = make_float4(0.f, 0.f, 0.f, 0.f);
        int qr = qb + row;
        if (qr < SEQ) v = *(const float4*)(g_q + qr * DIM + h * HD + d4);
        *(uint2*)&Qh[row * QSTR + d4] =
            pack_h4(v.x * scale, v.y * scale, v.z * scale, v.w * scale);
    }
    if (tid < 64) { Mi[tid] = -1e30f; Li[tid] = 0.f; }

    float oacc[8][4];
#pragma unroll
    for (int i = 0; i < 8; i++)
#pragma unroll
        for (int j = 0; j < 4; j++) oacc[i][j] = 0.f;
    __syncthreads();

    const int kbase0 = sp * (CACHE / KVSPLIT);
    for (int kb = 0; kb < KB_PER_SPLIT; kb++) {
        const int base = kbase0 + kb * 64;
#pragma unroll
        for (int i = 0; i < 8; i++) {
            int t = tid + i * 256;
            int row = t >> 5;
            int d4 = (t & 31) * 4;
            int kk = base + row;
            const float* kp;
            const float* vp;
            if (kk >= LSTART && kk < LEND) {
                int rr = kk - LSTART;
                kp = g_k + rr * DIM + h * HD;
                vp = g_v + rr * DIM + h * HD;
            } else {
                size_t off = ((size_t)kk * NH + h) * HD;
                kp = cache_k + off;
                vp = cache_v + off;
            }
            float4 kv = *(const float4*)(kp + d4);
            float4 vv = *(const float4*)(vp + d4);
            *(uint2*)&Kh[row * QSTR + d4] = pack_h4(kv.x, kv.y, kv.z, kv.w);
            *(uint2*)&Vh[row * QSTR + d4] = pack_h4(vv.x, vv.y, vv.z, vv.w);
        }
        __syncthreads();

        // S = Q @ K^T (64x64x128)
        float sacc[4][4];
#pragma unroll
        for (int i = 0; i < 4; i++)
#pragma unroll
            for (int j = 0; j < 4; j++) sacc[i][j] = 0.f;
#pragma unroll
        for (int kk = 0; kk < 8; kk++) {
            uint32_t a0, a1, a2, a3;
            uint32_t aaddr = uQ + ((wm * 16 + a_row) * QSTR + kk * 16) * 2 + a_coff;
            LDSM4(a0, a1, a2, a3, aaddr);
#pragma unroll
            for (int nt = 0; nt < 4; nt++) {
                uint32_t b0, b1;
                uint32_t baddr =
                    uK + ((wn * 32 + nt * 8 + b_row) * QSTR + kk * 16) * 2 + b_coff;
                LDSM2(b0, b1, baddr);
                mma_f16(sacc[nt], a0, a1, a2, a3, b0, b1);
            }
        }
        __syncthreads();  // Kh reads done before Sb (alias) writes

        {
            int r0 = wm * 16 + lr;
#pragma unroll
            for (int nt = 0; nt < 4; nt++) {
                int c = wn * 32 + nt * 8 + 2 * lc;
                Sb[r0 * SBSTR + c]     = sacc[nt][0];
                Sb[r0 * SBSTR + c + 1] = sacc[nt][1];
                Sb[(r0 + 8) * SBSTR + c]     = sacc[nt][2];
                Sb[(r0 + 8) * SBSTR + c + 1] = sacc[nt][3];
            }
        }
        __syncthreads();

        // Online softmax: 4 threads per row; write P as fp16
        {
            int r = tid >> 2;
            int jj = tid & 3;
            float* srow = Sb + r * SBSTR + jj * 16;
            __half2* prow = (__half2*)(Ph + r * PSTR + jj * 16);
            float mx = srow[0];
#pragma unroll
            for (int c = 1; c < 16; c++) mx = fmaxf(mx, srow[c]);
            mx = fmaxf(mx, __shfl_xor_sync(0xffffffffu, mx, 1));
            mx = fmaxf(mx, __shfl_xor_sync(0xffffffffu, mx, 2));
            float oldm = Mi[r];
            float newm = fmaxf(oldm, mx);
            float sum = 0.f;
#pragma unroll
            for (int c = 0; c < 8; c++) {
                float p0 = __expf(srow[2 * c] - newm);
                float p1 = __expf(srow[2 * c + 1] - newm);
                sum += p0 + p1;
                prow[c] = __floats2half2_rn(p0, p1);
            }
            sum += __shfl_xor_sync(0xffffffffu, sum, 1);
            sum += __shfl_xor_sync(0xffffffffu, sum, 2);
            if (jj == 0) {
                Al[r] = __expf(oldm - newm);
                Mi[r] = newm;
                Li[r] = Li[r] * Al[r] + sum;
            }
        }
        __syncthreads();

        // Rescale accumulators, then O += P @ V (64x128x64)
        {
            float al0 = Al[wm * 16 + lr];
            float al1 = Al[wm * 16 + lr + 8];
#pragma unroll
            for (int nt = 0; nt < 8; nt++) {
                oacc[nt][0] *= al0; oacc[nt][1] *= al0;
                oacc[nt][2] *= al1; oacc[nt][3] *= al1;
            }
        }
#pragma unroll
        for (int kk = 0; kk < 4; kk++) {
            uint32_t a0, a1, a2, a3;
            uint32_t paddr = uP + ((wm * 16 + a_row) * PSTR + kk * 16) * 2 + a_coff;
            LDSM4(a0, a1, a2, a3, paddr);
#pragma unroll
            for (int nt = 0; nt < 8; nt++) {
                uint32_t b0, b1;
                uint32_t vaddr =
                    uV + ((kk * 16 + (lane & 15)) * QSTR + wn * 64 + nt * 8) * 2;
                LDSM2T(b0, b1, vaddr);
                mma_f16(oacc[nt], a0, a1, a2, a3, b0, b1);
            }
        }
        __syncthreads();  // Vh/Ph reads done before next iter's stores
    }

    // Store unnormalized partial + per-row stats
    {
        float* pout = g_part + (size_t)sp * SEQ * DIM;
        int r0 = qb + wm * 16 + lr;
#pragma unroll
        for (int nt = 0; nt < 8; nt++) {
            int c = h * HD + wn * 64 + nt * 8 + 2 * lc;
            if (r0 < SEQ)
                *(float2*)(pout + (size_t)r0 * DIM + c) =
                    make_float2(oacc[nt][0], oacc[nt][1]);
            if (r0 + 8 < SEQ)
                *(float2*)(pout + (size_t)(r0 + 8) * DIM + c) =
                    make_float2(oacc[nt][2], oacc[nt][3]);
        }
        if (tid < 64 && qb + tid < SEQ) {
            g_m[(sp * NH + h) * SEQ + qb + tid] = Mi[tid];
            g_l[(sp * NH + h) * SEQ + qb + tid] = Li[tid];
        }
    }
}

// ---------------------------------------------------------------------------
// Combine KV-split partials -> g_attn
// ---------------------------------------------------------------------------
__global__ __launch_bounds__(256) void combine_kernel()
{
    const int row = blockIdx.x;
    const int tid = threadIdx.x;
    const int h = tid >> 4;
    const int d0 = (tid & 15) * 8;

    float m0 = g_m[(0 * NH + h) * SEQ + row];
    float m1 = g_m[(1 * NH + h) * SEQ + row];
    float m2 = g_m[(2 * NH + h) * SEQ + row];
    float M = fmaxf(m0, fmaxf(m1, m2));
    float w0 = __expf(m0 - M);
    float w1 = __expf(m1 - M);
    float w2 = __expf(m2 - M);
    float L = w0 * g_l[(0 * NH + h) * SEQ + row] +
              w1 * g_l[(1 * NH + h) * SEQ + row] +
              w2 * g_l[(2 * NH + h) * SEQ + row];
    float inv = 1.f / L;

    size_t base = (size_t)row * DIM + h * HD + d0;
    const size_t stride = (size_t)SEQ * DIM;
#pragma unroll
    for (int half = 0; half < 2; half++) {
        float4 p0 = *(const float4*)(g_part + base + half * 4);
        float4 p1 = *(const float4*)(g_part + stride + base + half * 4);
        float4 p2 = *(const float4*)(g_part + 2 * stride + base + half * 4);
        float4 o;
        o.x = (w0 * p0.x + w1 * p1.x + w2 * p2.x) * inv;
        o.y = (w0 * p0.y + w1 * p1.y + w2 * p2.y) * inv;
        o.z = (w0 * p0.z + w1 * p1.z + w2 * p2.z) * inv;
        o.w = (w0 * p0.w + w1 * p1.w + w2 * p2.w) * inv;
        *(float4*)(g_attn + base + half * 4) = o;
    }
}

// ---------------------------------------------------------------------------
extern "C" void kernel_launch(void* const* d_in, const int* in_sizes, int n_in,
                              void* d_out, int out_size)
{
    const float* x    = (const float*)d_in[0];
    const float* q_w  = (const float*)d_in[1];
    const float* q_b  = (const float*)d_in[2];
    const float* k_w  = (const float*)d_in[3];
    const float* k_b  = (const float*)d_in[4];
    const float* v_w  = (const float*)d_in[5];
    const float* v_b  = (const float*)d_in[6];
    const float* o_w  = (const float*)d_in[7];
    const float* o_b  = (const float*)d_in[8];
    const float* nqw  = (const float*)d_in[9];
    const float* nkw  = (const float*)d_in[10];
    const float* ck   = (const float*)d_in[11];
    const float* cv   = (const float*)d_in[12];
    const float* fc   = (const float*)d_in[13];
    const float* fs   = (const float*)d_in[14];

    float *dq, *dk, *dv, *da;
    cudaGetSymbolAddress((void**)&dq, g_q);
    cudaGetSymbolAddress((void**)&dk, g_k);
    cudaGetSymbolAddress((void**)&dv, g_v);
    cudaGetSymbolAddress((void**)&da, g_attn);

    // Fused QKV projection (fp16 ldmatrix + m16n8k16)
    GemmSet sq{q_w, q_b, dq}, sk{k_w, k_b, dk}, sv{v_w, v_b, dv};
    gemm_f16<<<dim3(16, 6, 3), 256>>>(x, sq, sk, sv, SEQ);

    // RMSNorm + RoPE (q and k, in place, fp32)
    rmsnorm_rope<<<dim3(SEQ, 2), 256>>>(nqw, nkw, fc, fs);

    // Attention (fp16 ldmatrix + m16n8k16, KV-split=3)
    const int ATTN_SMEM = 3 * 64 * QSTR * 2 + 64 * PSTR * 2 + 3 * 64 * 4; // 62208
    cudaFuncSetAttribute(attn_fp16, cudaFuncAttributeMaxDynamicSharedMemorySize,
                         ATTN_SMEM);
    attn_fp16<<<dim3(12, NH, KVSPLIT), 256, ATTN_SMEM>>>(ck, cv);

    // Merge splits
    combine_kernel<<<SEQ, 256>>>();

    // Output projection -> d_out (fp16 ldmatrix + m16n8k16)
    GemmSet so{o_w, o_b, (float*)d_out};
    gemm_f16<<<dim3(16, 6, 1), 256>>>(da, so, so, so, SEQ);
}

// round 6
// speedup vs baseline: 8.8726x; 1.6501x over previous
#include <cuda_runtime.h>
#include <cuda_fp16.h>
#include <cstdint>

#define SEQ    720
#define DIM    2048
#define NH     16
#define HD     128
#define CACHE  11520
#define LSTART 720
#define LEND   1440
#define KVSPLIT 3
#define KB_PER_SPLIT (CACHE / KVSPLIT / 64)   // 60

#define GSTR 40    // gemm smem halves per row (80 B)
#define KSTR 136   // attn smem halves per row (272 B)

// Scratch (device globals: allocation-free rule)
__device__ float g_q[SEQ * DIM];
__device__ float g_k[SEQ * DIM];
__device__ float g_v[SEQ * DIM];
__device__ float g_attn[SEQ * DIM];
__device__ float g_part[KVSPLIT * SEQ * DIM];
__device__ float g_m[KVSPLIT * NH * SEQ];
__device__ float g_l[KVSPLIT * NH * SEQ];
__device__ __half g_kh[(size_t)CACHE * DIM];   // head-major fp16 K cache
__device__ __half g_vh[(size_t)CACHE * DIM];   // head-major fp16 V cache

// ---------------------------------------------------------------------------
// helpers
// ---------------------------------------------------------------------------
__device__ __forceinline__ void mma_f16(float* c, uint32_t a0, uint32_t a1,
                                        uint32_t a2, uint32_t a3,
                                        uint32_t b0, uint32_t b1) {
    asm volatile(
        "mma.sync.aligned.m16n8k16.row.col.f32.f16.f16.f32 "
        "{%0,%1,%2,%3},{%4,%5,%6,%7},{%8,%9},{%0,%1,%2,%3};\n"
        : "+f"(c[0]), "+f"(c[1]), "+f"(c[2]), "+f"(c[3])
        : "r"(a0), "r"(a1), "r"(a2), "r"(a3), "r"(b0), "r"(b1));
}

__device__ __forceinline__ uint32_t sm_u32(const void* p) {
    uint32_t a;
    asm("{ .reg .u64 t; cvta.to.shared.u64 t, %1; cvt.u32.u64 %0, t; }"
        : "=r"(a) : "l"(p));
    return a;
}

#define LDSM4(r0_, r1_, r2_, r3_, a_) \
    asm volatile("ldmatrix.sync.aligned.m8n8.x4.shared.b16 {%0,%1,%2,%3}, [%4];" \
                 : "=r"(r0_), "=r"(r1_), "=r"(r2_), "=r"(r3_) : "r"(a_))
#define LDSM2(r0_, r1_, a_) \
    asm volatile("ldmatrix.sync.aligned.m8n8.x2.shared.b16 {%0,%1}, [%2];" \
                 : "=r"(r0_), "=r"(r1_) : "r"(a_))
#define LDSM4T(r0_, r1_, r2_, r3_, a_) \
    asm volatile("ldmatrix.sync.aligned.m8n8.x4.trans.shared.b16 {%0,%1,%2,%3}, [%4];" \
                 : "=r"(r0_), "=r"(r1_), "=r"(r2_), "=r"(r3_) : "r"(a_))

__device__ __forceinline__ uint2 pack_h4(float x, float y, float z, float w) {
    union { __half2 hh[2]; uint2 u; } pk;
    pk.hh[0] = __floats2half2_rn(x, y);
    pk.hh[1] = __floats2half2_rn(z, w);
    return pk.u;
}

__device__ __forceinline__ uint32_t pack_h2(float x, float y) {
    union { __half2 hh; uint32_t u; } pk;
    pk.hh = __floats2half2_rn(x, y);
    return pk.u;
}

__device__ __forceinline__ void cp_async16(uint32_t dst, const void* src) {
    asm volatile("cp.async.cg.shared.global [%0], [%1], 16;"
                 :: "r"(dst), "l"(src));
}
#define CP_COMMIT() asm volatile("cp.async.commit_group;" ::: "memory")
#define CP_WAIT(n)  asm volatile("cp.async.wait_group %0;" :: "n"(n) : "memory")

// ---------------------------------------------------------------------------
// GEMM (NT, fp16 m16n8k16 + ldmatrix). Unchanged from R5 — known good.
// ---------------------------------------------------------------------------
struct GemmSet {
    const float* B;
    const float* bias;
    float* C;
};

__global__ __launch_bounds__(256, 2) void gemm_f16(
    const float* __restrict__ A, GemmSet s0, GemmSet s1, GemmSet s2, int M)
{
    GemmSet s = (blockIdx.z == 0) ? s0 : ((blockIdx.z == 1) ? s1 : s2);

    __shared__ __half Ah[128 * GSTR];
    __shared__ __half Bh[128 * GSTR];
    const uint32_t uA = sm_u32(Ah);
    const uint32_t uB = sm_u32(Bh);

    const int tid  = threadIdx.x;
    const int lane = tid & 31;
    const int wid  = tid >> 5;
    const int wm   = wid >> 2;
    const int wn   = wid & 3;
    const int lr   = lane >> 2;
    const int lc   = lane & 3;
    const int bm = blockIdx.y * 128;
    const int bn = blockIdx.x * 128;

    const uint32_t a_row = (uint32_t)(lane & 15);
    const uint32_t a_coff = (uint32_t)((lane >> 4) * 8) * 2;
    const uint32_t b_row = (uint32_t)(lane & 7);
    const uint32_t b_coff = (uint32_t)(((lane >> 3) & 1) * 8) * 2;

    float acc[4][4][4];
#pragma unroll
    for (int i = 0; i < 4; i++)
#pragma unroll
        for (int j = 0; j < 4; j++)
#pragma unroll
            for (int q = 0; q < 4; q++) acc[i][j][q] = 0.f;

    const int lrow = tid >> 3;
    const int lcol = (tid & 7) * 4;
    bool aok[4];
    const float* Ap[4];
    const float* Bp[4];
#pragma unroll
    for (int i = 0; i < 4; i++) {
        int row = lrow + i * 32;
        aok[i] = (bm + row) < M;
        Ap[i] = A + (size_t)(bm + row) * 2048 + lcol;
        Bp[i] = s.B + (size_t)(bn + row) * 2048 + lcol;
    }

    float4 ra[4], rb[4];
#pragma unroll
    for (int i = 0; i < 4; i++) {
        ra[i] = aok[i] ? *(const float4*)Ap[i] : make_float4(0, 0, 0, 0);
        rb[i] = *(const float4*)Bp[i];
    }

    for (int k0 = 0; k0 < 2048; k0 += 32) {
#pragma unroll
        for (int i = 0; i < 4; i++) {
            int row = lrow + i * 32;
            *(uint2*)&Ah[row * GSTR + lcol] = pack_h4(ra[i].x, ra[i].y, ra[i].z, ra[i].w);
            *(uint2*)&Bh[row * GSTR + lcol] = pack_h4(rb[i].x, rb[i].y, rb[i].z, rb[i].w);
        }
        __syncthreads();

        if (k0 + 32 < 2048) {
#pragma unroll
            for (int i = 0; i < 4; i++) {
                ra[i] = aok[i] ? *(const float4*)(Ap[i] + k0 + 32)
                               : make_float4(0, 0, 0, 0);
                rb[i] = *(const float4*)(Bp[i] + k0 + 32);
            }
        }

#pragma unroll
        for (int kk = 0; kk < 2; kk++) {
            uint32_t af[4][4];
            uint32_t bf[4][2];
#pragma unroll
            for (int mt = 0; mt < 4; mt++) {
                uint32_t aaddr =
                    uA + ((wm * 64 + mt * 16 + a_row) * GSTR + kk * 16) * 2 + a_coff;
                LDSM4(af[mt][0], af[mt][1], af[mt][2], af[mt][3], aaddr);
            }
#pragma unroll
            for (int nt = 0; nt < 4; nt++) {
                uint32_t baddr =
                    uB + ((wn * 32 + nt * 8 + b_row) * GSTR + kk * 16) * 2 + b_coff;
                LDSM2(bf[nt][0], bf[nt][1], baddr);
            }
#pragma unroll
            for (int mt = 0; mt < 4; mt++)
#pragma unroll
                for (int nt = 0; nt < 4; nt++)
                    mma_f16(acc[mt][nt], af[mt][0], af[mt][1], af[mt][2], af[mt][3],
                            bf[nt][0], bf[nt][1]);
        }
        __syncthreads();
    }

#pragma unroll
    for (int mt = 0; mt < 4; mt++) {
        int row = bm + wm * 64 + mt * 16 + lr;
#pragma unroll
        for (int nt = 0; nt < 4; nt++) {
            int col = bn + wn * 32 + nt * 8 + 2 * lc;
            float b0v = s.bias[col], b1v = s.bias[col + 1];
            if (row < M) {
                float2 o = make_float2(acc[mt][nt][0] + b0v, acc[mt][nt][1] + b1v);
                *(float2*)(s.C + (size_t)row * 2048 + col) = o;
            }
            if (row + 8 < M) {
                float2 o = make_float2(acc[mt][nt][2] + b0v, acc[mt][nt][3] + b1v);
                *(float2*)(s.C + (size_t)(row + 8) * 2048 + col) = o;
            }
        }
    }
}

// ---------------------------------------------------------------------------
// RMSNorm + RoPE, in place on g_q (blockIdx.y=0) / g_k (blockIdx.y=1)
// ---------------------------------------------------------------------------
__global__ __launch_bounds__(256) void rmsnorm_rope(
    const float* __restrict__ wq, const float* __restrict__ wk,
    const float* __restrict__ fc, const float* __restrict__ fs)
{
    const int s = blockIdx.x;
    float* row = (blockIdx.y == 0 ? g_q : g_k) + s * DIM;
    const float* w = (blockIdx.y == 0) ? wq : wk;
    const int tid = threadIdx.x;

    float4 v0 = ((const float4*)row)[tid * 2];
    float4 v1 = ((const float4*)row)[tid * 2 + 1];
    float ss = v0.x * v0.x + v0.y * v0.y + v0.z * v0.z + v0.w * v0.w +
               v1.x * v1.x + v1.y * v1.y + v1.z * v1.z + v1.w * v1.w;
#pragma unroll
    for (int o = 16; o > 0; o >>= 1) ss += __shfl_xor_sync(0xffffffffu, ss, o);

    __shared__ float red[8];
    __shared__ float stot;
    if ((tid & 31) == 0) red[tid >> 5] = ss;
    __syncthreads();
    if (tid == 0) {
        float t = 0.f;
#pragma unroll
        for (int i = 0; i < 8; i++) t += red[i];
        stot = t;
    }
    __syncthreads();
    const float r = rsqrtf(stot * (1.0f / DIM) + 1e-6f);

    const int e = tid * 8;
    float xv[8] = {v0.x, v0.y, v0.z, v0.w, v1.x, v1.y, v1.z, v1.w};
    float ov[8];
#pragma unroll
    for (int i = 0; i < 4; i++) {
        int e0 = e + 2 * i;
        int j = (e0 & 127) >> 1;
        float c = fc[s * 64 + j];
        float sn = fs[s * 64 + j];
        float a = xv[2 * i] * r * w[e0];
        float b = xv[2 * i + 1] * r * w[e0 + 1];
        ov[2 * i] = a * c - b * sn;
        ov[2 * i + 1] = a * sn + b * c;
    }
    ((float4*)row)[tid * 2] = make_float4(ov[0], ov[1], ov[2], ov[3]);
    ((float4*)row)[tid * 2 + 1] = make_float4(ov[4], ov[5], ov[6], ov[7]);
}

// ---------------------------------------------------------------------------
// KV cache -> fp16, head-major [h][token][d], rolling window substituted.
// One block per token, 256 threads x 8 elems.
// ---------------------------------------------------------------------------
__global__ __launch_bounds__(256) void kvconv(
    const float* __restrict__ ck, const float* __restrict__ cv)
{
    const int t = blockIdx.x;
    const int tid = threadIdx.x;
    const float* srcK;
    const float* srcV;
    if (t >= LSTART && t < LEND) {
        srcK = g_k + (size_t)(t - LSTART) * DIM;
        srcV = g_v + (size_t)(t - LSTART) * DIM;
    } else {
        srcK = ck + (size_t)t * DIM;
        srcV = cv + (size_t)t * DIM;
    }
    const int e = tid * 8;
    const int h = e >> 7;
    const int d = e & 127;
    const size_t dst = ((size_t)h * CACHE + t) * HD + d;

    float4 a = *(const float4*)(srcK + e);
    float4 b = *(const float4*)(srcK + e + 4);
    uint4 o;
    o.x = pack_h2(a.x, a.y); o.y = pack_h2(a.z, a.w);
    o.z = pack_h2(b.x, b.y); o.w = pack_h2(b.z, b.w);
    *(uint4*)&g_kh[dst] = o;

    a = *(const float4*)(srcV + e);
    b = *(const float4*)(srcV + e + 4);
    o.x = pack_h2(a.x, a.y); o.y = pack_h2(a.z, a.w);
    o.z = pack_h2(b.x, b.y); o.w = pack_h2(b.z, b.w);
    *(uint4*)&g_vh[dst] = o;
}

// ---------------------------------------------------------------------------
// Flash attention v2-style: q-tile 128, 8 warps x 16 rows, register softmax,
// P reused from accumulators, cp.async double-buffered fp16 KV tiles.
// smem: Qh 128xKSTR | K stage0/1 64xKSTR | V stage0/1 64xKSTR
// ---------------------------------------------------------------------------
__global__ __launch_bounds__(256, 2) void attn_fa2()
{
    extern __shared__ char smc[];
    __half* Qh = (__half*)smc;                       // 128*KSTR
    const uint32_t uQ = sm_u32(smc);
    const uint32_t uK0 = uQ + 128 * KSTR * 2;
    const uint32_t uV0 = uK0 + 2 * 64 * KSTR * 2;    // after both K stages

    const int tid  = threadIdx.x;
    const int lane = tid & 31;
    const int wid  = tid >> 5;
    const int lr   = lane >> 2;
    const int lc   = lane & 3;
    const int h  = blockIdx.y;
    const int qb = blockIdx.x * 128;
    const int sp = blockIdx.z;
    const float scale = 0.08838834764831845f;  // 128^-0.5

    const uint32_t a_row = (uint32_t)(lane & 15);
    const uint32_t a_coff = (uint32_t)((lane >> 4) * 8) * 2;

    // K ldmatrix x4 (non-trans): rows = pair-of-ntiles, cols = k-chunk halves
    const uint32_t k_rowoff = (uint32_t)((lane >> 4) * 8 + (lane & 7));
    const uint32_t k_coloff = (uint32_t)(((lane >> 3) & 1) * 8);
    // V ldmatrix x4 (trans): rows = k, cols = pair-of-dtiles
    const uint32_t v_rowoff = (uint32_t)(lane & 15);
    const uint32_t v_coloff = (uint32_t)((lane >> 4) * 8);

    // Load Q tile (fp32 -> fp16, pre-scaled)
#pragma unroll
    for (int i = 0; i < 16; i++) {
        int t = tid + i * 256;
        int row = t >> 5;
        int d4 = (t & 31) * 4;
        float4 v = make_float4(0.f, 0.f, 0.f, 0.f);
        int qr = qb + row;
        if (qr < SEQ) v = *(const float4*)(g_q + (size_t)qr * DIM + h * HD + d4);
        *(uint2*)&Qh[row * KSTR + d4] =
            pack_h4(v.x * scale, v.y * scale, v.z * scale, v.w * scale);
    }

    float oacc[16][4];
#pragma unroll
    for (int i = 0; i < 16; i++)
#pragma unroll
        for (int j = 0; j < 4; j++) oacc[i][j] = 0.f;
    float m0 = -1e30f, m1 = -1e30f, l0 = 0.f, l1 = 0.f;

    const __half* baseK = g_kh + (size_t)h * CACHE * HD;
    const __half* baseV = g_vh + (size_t)h * CACHE * HD;
    const int tok0 = sp * (CACHE / KVSPLIT);

    // cp.async thread mapping: c = tid + i*256, row = c>>4, chunk = c&15 (16B)
    const int cp_row = tid >> 4;
    const int cp_ch  = (tid & 15);

    // issue tile 0 into stage 0
    {
        const __half* srcK = baseK + (size_t)tok0 * HD;
        const __half* srcV = baseV + (size_t)tok0 * HD;
#pragma unroll
        for (int i = 0; i < 4; i++) {
            int row = cp_row + i * 16;
            uint32_t doff = (uint32_t)(row * KSTR * 2 + cp_ch * 16);
            cp_async16(uK0 + doff, srcK + (size_t)row * HD + cp_ch * 8);
            cp_async16(uV0 + doff, srcV + (size_t)row * HD + cp_ch * 8);
        }
        CP_COMMIT();
    }

    for (int kb = 0; kb < KB_PER_SPLIT; kb++) {
        const int st = kb & 1;
        if (kb + 1 < KB_PER_SPLIT) {
            const int ns = (kb + 1) & 1;
            const __half* srcK = baseK + (size_t)(tok0 + (kb + 1) * 64) * HD;
            const __half* srcV = baseV + (size_t)(tok0 + (kb + 1) * 64) * HD;
#pragma unroll
            for (int i = 0; i < 4; i++) {
                int row = cp_row + i * 16;
                uint32_t doff = (uint32_t)(ns * 64 * KSTR * 2 + row * KSTR * 2 + cp_ch * 16);
                cp_async16(uK0 + doff, srcK + (size_t)row * HD + cp_ch * 8);
                cp_async16(uV0 + doff, srcV + (size_t)row * HD + cp_ch * 8);
            }
            CP_COMMIT();
            CP_WAIT(1);
        } else {
            CP_WAIT(0);
        }
        __syncthreads();

        const uint32_t uK = uK0 + st * 64 * KSTR * 2;
        const uint32_t uV = uV0 + st * 64 * KSTR * 2;

        // ---- S = Q @ K^T : warp rows wid*16..+15, all 64 keys ----
        float sacc[8][4];
#pragma unroll
        for (int i = 0; i < 8; i++)
#pragma unroll
            for (int j = 0; j < 4; j++) sacc[i][j] = 0.f;
#pragma unroll
        for (int kc = 0; kc < 8; kc++) {
            uint32_t a0, a1, a2, a3;
            uint32_t aaddr = uQ + ((wid * 16 + a_row) * KSTR + kc * 16) * 2 + a_coff;
            LDSM4(a0, a1, a2, a3, aaddr);
#pragma unroll
            for (int np = 0; np < 4; np++) {
                uint32_t b0, b1, b2, b3;
                uint32_t baddr =
                    uK + ((np * 16 + k_rowoff) * KSTR + kc * 16 + k_coloff) * 2;
                LDSM4(b0, b1, b2, b3, baddr);
                mma_f16(sacc[2 * np], a0, a1, a2, a3, b0, b1);
                mma_f16(sacc[2 * np + 1], a0, a1, a2, a3, b2, b3);
            }
        }

        // ---- online softmax in registers ----
        float mx0 = sacc[0][0], mx1 = sacc[0][2];
#pragma unroll
        for (int nt = 0; nt < 8; nt++) {
            mx0 = fmaxf(mx0, fmaxf(sacc[nt][0], sacc[nt][1]));
            mx1 = fmaxf(mx1, fmaxf(sacc[nt][2], sacc[nt][3]));
        }
        mx0 = fmaxf(mx0, __shfl_xor_sync(0xffffffffu, mx0, 1));
        mx0 = fmaxf(mx0, __shfl_xor_sync(0xffffffffu, mx0, 2));
        mx1 = fmaxf(mx1, __shfl_xor_sync(0xffffffffu, mx1, 1));
        mx1 = fmaxf(mx1, __shfl_xor_sync(0xffffffffu, mx1, 2));
        float nm0 = fmaxf(m0, mx0), nm1 = fmaxf(m1, mx1);
        float al0 = __expf(m0 - nm0), al1 = __expf(m1 - nm1);
        m0 = nm0; m1 = nm1;

        uint32_t pA[8], pB[8];   // packed P: rows lr / lr+8
        float sum0 = 0.f, sum1 = 0.f;
#pragma unroll
        for (int nt = 0; nt < 8; nt++) {
            float p0 = __expf(sacc[nt][0] - nm0);
            float p1 = __expf(sacc[nt][1] - nm0);
            float p2 = __expf(sacc[nt][2] - nm1);
            float p3 = __expf(sacc[nt][3] - nm1);
            sum0 += p0 + p1;
            sum1 += p2 + p3;
            pA[nt] = pack_h2(p0, p1);
            pB[nt] = pack_h2(p2, p3);
        }
        sum0 += __shfl_xor_sync(0xffffffffu, sum0, 1);
        sum0 += __shfl_xor_sync(0xffffffffu, sum0, 2);
        sum1 += __shfl_xor_sync(0xffffffffu, sum1, 1);
        sum1 += __shfl_xor_sync(0xffffffffu, sum1, 2);
        l0 = l0 * al0 + sum0;
        l1 = l1 * al1 + sum1;

#pragma unroll
        for (int nt = 0; nt < 16; nt++) {
            oacc[nt][0] *= al0; oacc[nt][1] *= al0;
            oacc[nt][2] *= al1; oacc[nt][3] *= al1;
        }

        // ---- O += P @ V : P fragments straight from registers ----
#pragma unroll
        for (int kc = 0; kc < 4; kc++) {
            uint32_t a0 = pA[2 * kc], a1 = pB[2 * kc];
            uint32_t a2 = pA[2 * kc + 1], a3 = pB[2 * kc + 1];
#pragma unroll
            for (int np = 0; np < 8; np++) {
                uint32_t b0, b1, b2, b3;
                uint32_t vaddr =
                    uV + ((kc * 16 + v_rowoff) * KSTR + np * 16 + v_coloff) * 2;
                LDSM4T(b0, b1, b2, b3, vaddr);
                mma_f16(oacc[2 * np], a0, a1, a2, a3, b0, b1);
                mma_f16(oacc[2 * np + 1], a0, a1, a2, a3, b2, b3);
            }
        }
        __syncthreads();
    }

    // Store unnormalized partial + stats
    {
        float* pout = g_part + (size_t)sp * SEQ * DIM;
        int r0 = qb + wid * 16 + lr;
#pragma unroll
        for (int nt = 0; nt < 16; nt++) {
            int c = h * HD + nt * 8 + 2 * lc;
            if (r0 < SEQ)
                *(float2*)(pout + (size_t)r0 * DIM + c) =
                    make_float2(oacc[nt][0], oacc[nt][1]);
            if (r0 + 8 < SEQ)
                *(float2*)(pout + (size_t)(r0 + 8) * DIM + c) =
                    make_float2(oacc[nt][2], oacc[nt][3]);
        }
        if (lc == 0) {
            if (r0 < SEQ) {
                g_m[(sp * NH + h) * SEQ + r0] = m0;
                g_l[(sp * NH + h) * SEQ + r0] = l0;
            }
            if (r0 + 8 < SEQ) {
                g_m[(sp * NH + h) * SEQ + r0 + 8] = m1;
                g_l[(sp * NH + h) * SEQ + r0 + 8] = l1;
            }
        }
    }
}

// ---------------------------------------------------------------------------
// Combine KV-split partials -> g_attn
// ---------------------------------------------------------------------------
__global__ __launch_bounds__(256) void combine_kernel()
{
    const int row = blockIdx.x;
    const int tid = threadIdx.x;
    const int h = tid >> 4;
    const int d0 = (tid & 15) * 8;

    float m0 = g_m[(0 * NH + h) * SEQ + row];
    float m1 = g_m[(1 * NH + h) * SEQ + row];
    float m2 = g_m[(2 * NH + h) * SEQ + row];
    float M = fmaxf(m0, fmaxf(m1, m2));
    float w0 = __expf(m0 - M);
    float w1 = __expf(m1 - M);
    float w2 = __expf(m2 - M);
    float L = w0 * g_l[(0 * NH + h) * SEQ + row] +
              w1 * g_l[(1 * NH + h) * SEQ + row] +
              w2 * g_l[(2 * NH + h) * SEQ + row];
    float inv = 1.f / L;

    size_t base = (size_t)row * DIM + h * HD + d0;
    const size_t stride = (size_t)SEQ * DIM;
#pragma unroll
    for (int half = 0; half < 2; half++) {
        float4 p0 = *(const float4*)(g_part + base + half * 4);
        float4 p1 = *(const float4*)(g_part + stride + base + half * 4);
        float4 p2 = *(const float4*)(g_part + 2 * stride + base + half * 4);
        float4 o;
        o.x = (w0 * p0.x + w1 * p1.x + w2 * p2.x) * inv;
        o.y = (w0 * p0.y + w1 * p1.y + w2 * p2.y) * inv;
        o.z = (w0 * p0.z + w1 * p1.z + w2 * p2.z) * inv;
        o.w = (w0 * p0.w + w1 * p1.w + w2 * p2.w) * inv;
        *(float4*)(g_attn + base + half * 4) = o;
    }
}

// ---------------------------------------------------------------------------
extern "C" void kernel_launch(void* const* d_in, const int* in_sizes, int n_in,
                              void* d_out, int out_size)
{
    const float* x    = (const float*)d_in[0];
    const float* q_w  = (const float*)d_in[1];
    const float* q_b  = (const float*)d_in[2];
    const float* k_w  = (const float*)d_in[3];
    const float* k_b  = (const float*)d_in[4];
    const float* v_w  = (const float*)d_in[5];
    const float* v_b  = (const float*)d_in[6];
    const float* o_w  = (const float*)d_in[7];
    const float* o_b  = (const float*)d_in[8];
    const float* nqw  = (const float*)d_in[9];
    const float* nkw  = (const float*)d_in[10];
    const float* ck   = (const float*)d_in[11];
    const float* cv   = (const float*)d_in[12];
    const float* fc   = (const float*)d_in[13];
    const float* fs   = (const float*)d_in[14];

    float *dq, *dk, *dv, *da;
    cudaGetSymbolAddress((void**)&dq, g_q);
    cudaGetSymbolAddress((void**)&dk, g_k);
    cudaGetSymbolAddress((void**)&dv, g_v);
    cudaGetSymbolAddress((void**)&da, g_attn);

    // Fused QKV projection (fp16 ldmatrix + m16n8k16)
    GemmSet sq{q_w, q_b, dq}, sk{k_w, k_b, dk}, sv{v_w, v_b, dv};
    gemm_f16<<<dim3(16, 6, 3), 256>>>(x, sq, sk, sv, SEQ);

    // RMSNorm + RoPE (q and k, in place, fp32)
    rmsnorm_rope<<<dim3(SEQ, 2), 256>>>(nqw, nkw, fc, fs);

    // Build fp16 head-major KV caches (with rolling-window substitution)
    kvconv<<<CACHE, 256>>>(ck, cv);

    // Attention (FA2-style, cp.async pipelined, KV-split=3)
    const int ATTN_SMEM = (128 * KSTR + 4 * 64 * KSTR) * 2;   // 104448
    cudaFuncSetAttribute(attn_fa2, cudaFuncAttributeMaxDynamicSharedMemorySize,
                         ATTN_SMEM);
    attn_fa2<<<dim3((SEQ + 127) / 128, NH, KVSPLIT), 256, ATTN_SMEM>>>();

    // Merge splits
    combine_kernel<<<SEQ, 256>>>();

    // Output projection -> d_out (fp16 ldmatrix + m16n8k16)
    GemmSet so{o_w, o_b, (float*)d_out};
    gemm_f16<<<dim3(16, 6, 1), 256>>>(da, so, so, so, SEQ);
}